// round 3
// baseline (speedup 1.0000x reference)
#include <cuda_runtime.h>
#include <math.h>

#define NB   128
#define SEQL 197
#define NPAT 196
#define HD   768
#define NH   12
#define DH   64
#define LN_EPS 1e-5f

// ---------------- scratch (static device globals; no allocs) ----------------
static __device__ float g_tokens[NB * SEQL * HD];          // 77.4 MB
static __device__ float g_pos[SEQL * HD];
static __device__ float g_mean[NB];
static __device__ float g_rstd[NB];
static __device__ float g_q[NB * NH * SEQL * DH];          // [b][h][s][e]
static __device__ float g_k[NB * NH * SEQL * DH];
static __device__ float g_v[NB * NH * SEQL * DH];

// ---------------- positional embeddings ----------------
__global__ void pos_kernel() {
    int idx = blockIdx.x * blockDim.x + threadIdx.x;
    if (idx >= SEQL * HD) return;
    int i = idx / HD, j = idx % HD;
    float jf = (float)(j & ~1);
    float denom = powf(10000.0f, jf / (float)HD);
    float arg = (float)i / denom;
    g_pos[idx] = (j & 1) ? cosf(arg) : sinf(arg);
}

// ---------------- class token row ----------------
__global__ void cls_kernel(const float* __restrict__ cls) {
    int b = blockIdx.x;
    for (int j = threadIdx.x; j < HD; j += blockDim.x)
        g_tokens[(size_t)b * SEQL * HD + j] = cls[j] + g_pos[j];
}

// ---------------- token projection GEMM ----------------
// C[m,n] = sum_k A[m,k] * W[n,k];  A = images viewed [25088, 768], W = W_map [768, 768]
// 64x64 block tile, 16 k-tile, 256 threads, 4x4 per-thread microtile.
__global__ __launch_bounds__(256) void gemm_tokens(const float* __restrict__ A,
                                                   const float* __restrict__ W,
                                                   const float* __restrict__ bias) {
    __shared__ float As[16][68];
    __shared__ float Bs[16][68];
    const int tid  = threadIdx.x;
    const int rowL = tid >> 2;
    const int kL   = (tid & 3) * 4;
    const int tx   = tid & 15, ty = tid >> 4;
    const int m0 = blockIdx.x * 64;
    const int n0 = blockIdx.y * 64;
    const float* Ab = A + (size_t)(m0 + rowL) * HD + kL;
    const float* Wb = W + (size_t)(n0 + rowL) * HD + kL;

    float acc[4][4] = {};
    for (int kt = 0; kt < HD; kt += 16) {
        float4 a4 = *(const float4*)(Ab + kt);
        float4 b4 = *(const float4*)(Wb + kt);
        As[kL + 0][rowL] = a4.x; As[kL + 1][rowL] = a4.y;
        As[kL + 2][rowL] = a4.z; As[kL + 3][rowL] = a4.w;
        Bs[kL + 0][rowL] = b4.x; Bs[kL + 1][rowL] = b4.y;
        Bs[kL + 2][rowL] = b4.z; Bs[kL + 3][rowL] = b4.w;
        __syncthreads();
#pragma unroll
        for (int kk = 0; kk < 16; kk++) {
            float4 av = *(const float4*)&As[kk][ty * 4];
            float4 bv = *(const float4*)&Bs[kk][tx * 4];
            float a[4] = {av.x, av.y, av.z, av.w};
            float bb[4] = {bv.x, bv.y, bv.z, bv.w};
#pragma unroll
            for (int i = 0; i < 4; i++)
#pragma unroll
                for (int j = 0; j < 4; j++) acc[i][j] += a[i] * bb[j];
        }
        __syncthreads();
    }
    // epilogue: + b_map + pos, scatter to tokens rows 1..196
#pragma unroll
    for (int i = 0; i < 4; i++) {
        int mg = m0 + ty * 4 + i;
        int b = mg / NPAT, p = mg % NPAT;
        float* outr = g_tokens + ((size_t)b * SEQL + p + 1) * HD;
        const float* posr = g_pos + (size_t)(p + 1) * HD;
#pragma unroll
        for (int j = 0; j < 4; j++) {
            int n = n0 + tx * 4 + j;
            outr[n] = acc[i][j] + bias[n] + posr[n];
        }
    }
}

// ---------------- per-sample LN stats (mean/var over SEQ*D jointly) ----------------
__global__ __launch_bounds__(256) void stats_kernel() {
    int b = blockIdx.x;
    const float4* base = (const float4*)(g_tokens + (size_t)b * SEQL * HD);
    const int n4 = SEQL * HD / 4;  // 37824
    float s = 0.f, sq = 0.f;
    for (int i = threadIdx.x; i < n4; i += 256) {
        float4 v = base[i];
        s  += v.x + v.y + v.z + v.w;
        sq += v.x * v.x + v.y * v.y + v.z * v.z + v.w * v.w;
    }
    __shared__ float sh[64];
#pragma unroll
    for (int o = 16; o; o >>= 1) {
        s  += __shfl_xor_sync(0xffffffffu, s, o);
        sq += __shfl_xor_sync(0xffffffffu, sq, o);
    }
    int w = threadIdx.x >> 5, l = threadIdx.x & 31;
    if (!l) { sh[w] = s; sh[32 + w] = sq; }
    __syncthreads();
    if (threadIdx.x == 0) {
        float S = 0.f, Q = 0.f;
        for (int i = 0; i < 8; i++) { S += sh[i]; Q += sh[32 + i]; }
        const float n = (float)(SEQL * HD);
        float mean = S / n;
        float var  = Q / n - mean * mean;
        g_mean[b] = mean;
        g_rstd[b] = rsqrtf(var + LN_EPS);
    }
}

// ---------------- QKV projections (LN fused into the load) ----------------
// grid.x = b*NH+h, grid.y = {0:q, 1:k, 2:v}
#define XST 211
#define QKV_SMEM ((64 * XST + 64 * 68) * 4)
__global__ __launch_bounds__(256) void qkv_kernel(
    const float* __restrict__ lnw, const float* __restrict__ lnb,
    const float* __restrict__ Wq, const float* __restrict__ bq,
    const float* __restrict__ Wk, const float* __restrict__ bk,
    const float* __restrict__ Wv, const float* __restrict__ bv) {
    extern __shared__ float smem[];
    float* Xs = smem;             // [64][XST]  x normalized, d-major
    float* Wt = smem + 64 * XST;  // [64][68]   weight transposed, d-major

    int bh = blockIdx.x, b = bh / NH, h = bh % NH;
    int m = blockIdx.y;
    const float* W    = (m == 0 ? Wq : (m == 1 ? Wk : Wv)) + (size_t)h * DH * DH;
    const float* bias = (m == 0 ? bq : (m == 1 ? bk : bv)) + h * DH;
    float* outp = (m == 0 ? g_q : (m == 1 ? g_k : g_v)) + (size_t)bh * SEQL * DH;

    float mean = g_mean[b], rstd = g_rstd[b];
    const float* tb = g_tokens + (size_t)b * SEQL * HD + h * DH;

    for (int li = threadIdx.x; li < SEQL * 16; li += 256) {
        int s = li >> 4, d4 = (li & 15) * 4;
        float4 tv = *(const float4*)(tb + (size_t)s * HD + d4);
        float4 wv = *(const float4*)(lnw + (size_t)s * HD + h * DH + d4);
        float4 bb = *(const float4*)(lnb + (size_t)s * HD + h * DH + d4);
        Xs[(d4 + 0) * XST + s] = (tv.x - mean) * rstd * wv.x + bb.x;
        Xs[(d4 + 1) * XST + s] = (tv.y - mean) * rstd * wv.y + bb.y;
        Xs[(d4 + 2) * XST + s] = (tv.z - mean) * rstd * wv.z + bb.z;
        Xs[(d4 + 3) * XST + s] = (tv.w - mean) * rstd * wv.w + bb.w;
    }
    for (int li = threadIdx.x; li < 64 * 16; li += 256) {
        int e = li >> 4, d4 = (li & 15) * 4;
        float4 w4 = *(const float4*)(W + e * DH + d4);
        Wt[(d4 + 0) * 68 + e] = w4.x;
        Wt[(d4 + 1) * 68 + e] = w4.y;
        Wt[(d4 + 2) * 68 + e] = w4.z;
        Wt[(d4 + 3) * 68 + e] = w4.w;
    }
    __syncthreads();

    int tx = threadIdx.x & 15, ty = threadIdx.x >> 4;
    float acc[13][4] = {};
    for (int d = 0; d < 64; d++) {
        float4 w4 = *(const float4*)&Wt[d * 68 + tx * 4];
        const float* xr = &Xs[d * XST];
#pragma unroll
        for (int t = 0; t < 13; t++) {
            float xv = xr[ty + 16 * t];  // rows >=197 read garbage; stores guarded
            acc[t][0] += xv * w4.x;
            acc[t][1] += xv * w4.y;
            acc[t][2] += xv * w4.z;
            acc[t][3] += xv * w4.w;
        }
    }
    float4 b4 = *(const float4*)(bias + tx * 4);
#pragma unroll
    for (int t = 0; t < 13; t++) {
        int r = ty + 16 * t;
        if (r < SEQL) {
            float4 o = {acc[t][0] + b4.x, acc[t][1] + b4.y,
                        acc[t][2] + b4.z, acc[t][3] + b4.w};
            *(float4*)(outp + (size_t)r * DH + tx * 4) = o;
        }
    }
}

// ---------------- attention + residual (writes final output) ----------------
#define KS_FLOATS 12808  // 197*65 rounded up to multiple of 4 for float4 alignment of Vs
#define ATT_SMEM ((KS_FLOATS + SEQL * 64 + 8 * 64 + 8 * SEQL) * 4)
__global__ __launch_bounds__(256) void attn_kernel(float* __restrict__ out) {
    extern __shared__ float smem[];
    float* Ks = smem;                         // [197][65] (pad 65 -> conflict-free lane->t)
    float* Vs = smem + KS_FLOATS;             // [197][64]
    float* Qs = Vs + SEQL * 64;               // [8][64]
    float* Ps = Qs + 8 * 64;                  // [8][197]

    int bh = blockIdx.x, b = bh / NH, h = bh % NH;
    const float* kp = g_k + (size_t)bh * SEQL * DH;
    const float* vp = g_v + (size_t)bh * SEQL * DH;
    const float* qp = g_q + (size_t)bh * SEQL * DH;

    for (int li = threadIdx.x; li < SEQL * 16; li += 256) {
        int t = li >> 4, e4 = (li & 15) * 4;
        float4 kv = *(const float4*)(kp + (size_t)t * DH + e4);
        Ks[t * 65 + e4 + 0] = kv.x; Ks[t * 65 + e4 + 1] = kv.y;
        Ks[t * 65 + e4 + 2] = kv.z; Ks[t * 65 + e4 + 3] = kv.w;
        float4 vv = *(const float4*)(vp + (size_t)t * DH + e4);
        *(float4*)&Vs[t * 64 + e4] = vv;
    }
    __syncthreads();

    int w = threadIdx.x >> 5, l = threadIdx.x & 31;
    for (int s = w; s < SEQL; s += 8) {
        // stage q row, then spread to registers
        Qs[w * 64 + l]      = qp[(size_t)s * DH + l];
        Qs[w * 64 + l + 32] = qp[(size_t)s * DH + l + 32];
        __syncwarp();
        float q[64];
#pragma unroll
        for (int e4 = 0; e4 < 16; e4++) {
            float4 t4 = *(const float4*)&Qs[w * 64 + e4 * 4];
            q[e4 * 4 + 0] = t4.x; q[e4 * 4 + 1] = t4.y;
            q[e4 * 4 + 2] = t4.z; q[e4 * 4 + 3] = t4.w;
        }
        // scores: lane l handles t = l, l+32, ...
        float sc[7];
#pragma unroll
        for (int j = 0; j < 7; j++) {
            int t = l + 32 * j;
            if (t < SEQL) {
                const float* kr = &Ks[t * 65];
                float a = 0.f;
#pragma unroll
                for (int e = 0; e < 64; e++) a += q[e] * kr[e];
                sc[j] = a * 0.125f;  // 1/sqrt(64)
            } else sc[j] = -1e30f;
        }
        float mx = sc[0];
#pragma unroll
        for (int j = 1; j < 7; j++) mx = fmaxf(mx, sc[j]);
#pragma unroll
        for (int o = 16; o; o >>= 1) mx = fmaxf(mx, __shfl_xor_sync(0xffffffffu, mx, o));
        float ssum = 0.f;
#pragma unroll
        for (int j = 0; j < 7; j++) { sc[j] = expf(sc[j] - mx); ssum += sc[j]; }
#pragma unroll
        for (int o = 16; o; o >>= 1) ssum += __shfl_xor_sync(0xffffffffu, ssum, o);
        float inv = 1.0f / ssum;
#pragma unroll
        for (int j = 0; j < 7; j++) {
            int t = l + 32 * j;
            if (t < SEQL) Ps[w * SEQL + t] = sc[j] * inv;
        }
        __syncwarp();
        // AV: lane handles columns l and l+32
        float a0 = 0.f, a1 = 0.f;
        const float* pr = &Ps[w * SEQL];
#pragma unroll 4
        for (int t = 0; t < SEQL; t++) {
            float p = pr[t];
            a0 += p * Vs[t * 64 + l];
            a1 += p * Vs[t * 64 + l + 32];
        }
        size_t ob = ((size_t)b * SEQL + s) * HD + h * DH;
        out[ob + l]      = g_tokens[ob + l] + a0;
        out[ob + l + 32] = g_tokens[ob + l + 32] + a1;
        __syncwarp();
    }
}

// ---------------- launcher ----------------
extern "C" void kernel_launch(void* const* d_in, const int* in_sizes, int n_in,
                              void* d_out, int out_size) {
    const float* images = (const float*)d_in[0];
    const float* W_map  = (const float*)d_in[1];
    const float* b_map  = (const float*)d_in[2];
    const float* cls    = (const float*)d_in[3];
    const float* ln_w   = (const float*)d_in[4];
    const float* ln_b   = (const float*)d_in[5];
    const float* Wq     = (const float*)d_in[6];
    const float* bq     = (const float*)d_in[7];
    const float* Wk     = (const float*)d_in[8];
    const float* bk     = (const float*)d_in[9];
    const float* Wv     = (const float*)d_in[10];
    const float* bv     = (const float*)d_in[11];
    float* out = (float*)d_out;

    cudaFuncSetAttribute(qkv_kernel,  cudaFuncAttributeMaxDynamicSharedMemorySize, QKV_SMEM);
    cudaFuncSetAttribute(attn_kernel, cudaFuncAttributeMaxDynamicSharedMemorySize, ATT_SMEM);

    pos_kernel<<<(SEQL * HD + 255) / 256, 256>>>();
    cls_kernel<<<NB, 256>>>(cls);
    gemm_tokens<<<dim3((NB * NPAT) / 64, HD / 64), 256>>>(images, W_map, b_map);
    stats_kernel<<<NB, 256>>>();
    qkv_kernel<<<dim3(NB * NH, 3), 256, QKV_SMEM>>>(ln_w, ln_b, Wq, bq, Wk, bk, Wv, bv);
    attn_kernel<<<NB * NH, 256, ATT_SMEM>>>(out);
}

// round 6
// speedup vs baseline: 1.1896x; 1.1896x over previous
#include <cuda_runtime.h>
#include <cuda_bf16.h>
#include <math.h>
#include <stdint.h>

#define NB   128
#define SEQL 197
#define NPAT 196
#define HD   768
#define NH   12
#define DH   64
#define LN_EPS 1e-5f

// ---------------- scratch (static device globals; no allocs) ----------------
static __device__ float g_tokens[NB * SEQL * HD];          // 77.4 MB
static __device__ float g_pos[SEQL * HD];
static __device__ float g_mean[NB];
static __device__ float g_rstd[NB];
static __device__ float g_q[NB * NH * SEQL * DH];          // [b][h][s][e]
static __device__ float g_k[NB * NH * SEQL * DH];
static __device__ float g_v[NB * NH * SEQL * DH];

// ================= helpers =================
__device__ __forceinline__ uint32_t smem_u32(const void* p) {
    uint32_t a;
    asm("{ .reg .u64 t; cvta.to.shared.u64 t, %1; cvt.u32.u64 %0, t; }" : "=r"(a) : "l"(p));
    return a;
}
#define LDSM4(r, addr) \
    asm volatile("ldmatrix.sync.aligned.m8n8.x4.shared.b16 {%0,%1,%2,%3}, [%4];" \
        : "=r"((r)[0]), "=r"((r)[1]), "=r"((r)[2]), "=r"((r)[3]) : "r"(addr))

__device__ __forceinline__ void mma_bf16(float* c, const uint32_t* a, const uint32_t* b) {
    asm volatile("mma.sync.aligned.m16n8k16.row.col.f32.bf16.bf16.f32 "
        "{%0,%1,%2,%3}, {%4,%5,%6,%7}, {%8,%9}, {%0,%1,%2,%3};"
        : "+f"(c[0]), "+f"(c[1]), "+f"(c[2]), "+f"(c[3])
        : "r"(a[0]), "r"(a[1]), "r"(a[2]), "r"(a[3]), "r"(b[0]), "r"(b[1]));
}

__device__ __forceinline__ uint32_t pack_bf16(__nv_bfloat16 x, __nv_bfloat16 y) {
    __nv_bfloat162 t = {x, y};
    return *(uint32_t*)&t;
}

// ---------------- positional embeddings ----------------
__global__ void pos_kernel() {
    int idx = blockIdx.x * blockDim.x + threadIdx.x;
    if (idx >= SEQL * HD) return;
    int i = idx / HD, j = idx % HD;
    float jf = (float)(j & ~1);
    float denom = powf(10000.0f, jf / (float)HD);
    float arg = (float)i / denom;
    g_pos[idx] = (j & 1) ? cosf(arg) : sinf(arg);
}

// ---------------- class token row ----------------
__global__ void cls_kernel(const float* __restrict__ cls) {
    int b = blockIdx.x;
    for (int j = threadIdx.x; j < HD; j += blockDim.x)
        g_tokens[(size_t)b * SEQL * HD + j] = cls[j] + g_pos[j];
}

// ---------------- token projection GEMM via mma.sync bf16x3 ----------------
// C[m,n] = sum_k A[m,k] * W[n,k];  M=25088, N=768, K=768.
// CTA tile 128x64, BK=64, 8 warps (4m x 2n), warp tile 32x32.
// bf16x3: A,B split hi/lo; acc += Ahi*Bhi + Ahi*Blo + Alo*Bhi (fp32 accum).
#define KS 72  // padded smem row stride (bf16 elems): 144B -> conflict-free ldmatrix
#define GA_H 0
#define GA_L (128 * KS)
#define GB_H (256 * KS)
#define GB_L (320 * KS)
#define G_SMEM (384 * KS * 2)

__global__ __launch_bounds__(256) void gemm_tokens_mma(const float* __restrict__ A,
                                                       const float* __restrict__ Wm,
                                                       const float* __restrict__ bias) {
    extern __shared__ char smc[];
    __nv_bfloat16* sm = (__nv_bfloat16*)smc;
    const int tid  = threadIdx.x;
    const int lane = tid & 31, wid = tid >> 5;
    const int wm = wid & 3, wn = wid >> 2;
    const int m0 = blockIdx.x * 128;
    const int n0 = blockIdx.y * 64;

    float c[2][4][4] = {};

    for (int kt = 0; kt < HD; kt += 64) {
        // stage A tile 128x64 (fp32 -> bf16 hi/lo)
#pragma unroll
        for (int it = 0; it < 8; it++) {
            int idx = tid + it * 256;
            int row = idx >> 4, c4 = (idx & 15) * 4;
            float4 v = *(const float4*)(A + (size_t)(m0 + row) * HD + kt + c4);
            __nv_bfloat16 hx = __float2bfloat16(v.x), hy = __float2bfloat16(v.y);
            __nv_bfloat16 hz = __float2bfloat16(v.z), hw = __float2bfloat16(v.w);
            __nv_bfloat16 lx = __float2bfloat16(v.x - __bfloat162float(hx));
            __nv_bfloat16 ly = __float2bfloat16(v.y - __bfloat162float(hy));
            __nv_bfloat16 lz = __float2bfloat16(v.z - __bfloat162float(hz));
            __nv_bfloat16 lw = __float2bfloat16(v.w - __bfloat162float(hw));
            uint2 hp = {pack_bf16(hx, hy), pack_bf16(hz, hw)};
            uint2 lp = {pack_bf16(lx, ly), pack_bf16(lz, lw)};
            *(uint2*)&sm[GA_H + row * KS + c4] = hp;
            *(uint2*)&sm[GA_L + row * KS + c4] = lp;
        }
        // stage W tile 64x64
#pragma unroll
        for (int it = 0; it < 4; it++) {
            int idx = tid + it * 256;
            int row = idx >> 4, c4 = (idx & 15) * 4;
            float4 v = *(const float4*)(Wm + (size_t)(n0 + row) * HD + kt + c4);
            __nv_bfloat16 hx = __float2bfloat16(v.x), hy = __float2bfloat16(v.y);
            __nv_bfloat16 hz = __float2bfloat16(v.z), hw = __float2bfloat16(v.w);
            __nv_bfloat16 lx = __float2bfloat16(v.x - __bfloat162float(hx));
            __nv_bfloat16 ly = __float2bfloat16(v.y - __bfloat162float(hy));
            __nv_bfloat16 lz = __float2bfloat16(v.z - __bfloat162float(hz));
            __nv_bfloat16 lw = __float2bfloat16(v.w - __bfloat162float(hw));
            uint2 hp = {pack_bf16(hx, hy), pack_bf16(hz, hw)};
            uint2 lp = {pack_bf16(lx, ly), pack_bf16(lz, lw)};
            *(uint2*)&sm[GB_H + row * KS + c4] = hp;
            *(uint2*)&sm[GB_L + row * KS + c4] = lp;
        }
        __syncthreads();

#pragma unroll
        for (int ks = 0; ks < 4; ks++) {
            const int k0 = ks * 16;
            uint32_t ah[2][4], al[2][4], bh[4][2], bl[4][2];
            // A fragments: rows = m, lanes 0-15 -> rows 0-15 @k0, 16-31 -> rows @k0+8
#pragma unroll
            for (int mf = 0; mf < 2; mf++) {
                int r = wm * 32 + mf * 16 + (lane & 15);
                int ko = k0 + (lane >> 4) * 8;
                LDSM4(ah[mf], smem_u32(&sm[GA_H + r * KS + ko]));
                LDSM4(al[mf], smem_u32(&sm[GA_L + r * KS + ko]));
            }
            // B fragments: x4 covers two n8 frags (k-major rows = n)
#pragma unroll
            for (int nf2 = 0; nf2 < 2; nf2++) {
                int seg = lane >> 3;
                int r = wn * 32 + nf2 * 16 + (seg >> 1) * 8 + (lane & 7);
                int ko = k0 + (seg & 1) * 8;
                uint32_t t4[4];
                LDSM4(t4, smem_u32(&sm[GB_H + r * KS + ko]));
                bh[nf2 * 2 + 0][0] = t4[0]; bh[nf2 * 2 + 0][1] = t4[1];
                bh[nf2 * 2 + 1][0] = t4[2]; bh[nf2 * 2 + 1][1] = t4[3];
                LDSM4(t4, smem_u32(&sm[GB_L + r * KS + ko]));
                bl[nf2 * 2 + 0][0] = t4[0]; bl[nf2 * 2 + 0][1] = t4[1];
                bl[nf2 * 2 + 1][0] = t4[2]; bl[nf2 * 2 + 1][1] = t4[3];
            }
#pragma unroll
            for (int mf = 0; mf < 2; mf++)
#pragma unroll
                for (int nf = 0; nf < 4; nf++) {
                    mma_bf16(c[mf][nf], ah[mf], bh[nf]);
                    mma_bf16(c[mf][nf], ah[mf], bl[nf]);
                    mma_bf16(c[mf][nf], al[mf], bh[nf]);
                }
        }
        __syncthreads();
    }

    // epilogue: + bias + pos, scatter to g_tokens rows 1..196
#pragma unroll
    for (int mf = 0; mf < 2; mf++) {
#pragma unroll
        for (int half = 0; half < 2; half++) {
            int mg = m0 + wm * 32 + mf * 16 + (lane >> 2) + half * 8;
            int b = mg / NPAT, p = mg % NPAT;
            float* orow = g_tokens + ((size_t)b * SEQL + p + 1) * HD;
            const float* prow = g_pos + (size_t)(p + 1) * HD;
#pragma unroll
            for (int nf = 0; nf < 4; nf++) {
                int col = n0 + wn * 32 + nf * 8 + (lane & 3) * 2;
                float2 o;
                o.x = c[mf][nf][half * 2 + 0] + bias[col] + prow[col];
                o.y = c[mf][nf][half * 2 + 1] + bias[col + 1] + prow[col + 1];
                *(float2*)(orow + col) = o;
            }
        }
    }
}

// ---------------- per-sample LN stats (mean/var over SEQ*D jointly) ----------------
__global__ __launch_bounds__(256) void stats_kernel() {
    int b = blockIdx.x;
    const float4* base = (const float4*)(g_tokens + (size_t)b * SEQL * HD);
    const int n4 = SEQL * HD / 4;  // 37824
    float s = 0.f, sq = 0.f;
    for (int i = threadIdx.x; i < n4; i += 256) {
        float4 v = base[i];
        s  += v.x + v.y + v.z + v.w;
        sq += v.x * v.x + v.y * v.y + v.z * v.z + v.w * v.w;
    }
    __shared__ float sh[64];
#pragma unroll
    for (int o = 16; o; o >>= 1) {
        s  += __shfl_xor_sync(0xffffffffu, s, o);
        sq += __shfl_xor_sync(0xffffffffu, sq, o);
    }
    int w = threadIdx.x >> 5, l = threadIdx.x & 31;
    if (!l) { sh[w] = s; sh[32 + w] = sq; }
    __syncthreads();
    if (threadIdx.x == 0) {
        float S = 0.f, Q = 0.f;
        for (int i = 0; i < 8; i++) { S += sh[i]; Q += sh[32 + i]; }
        const float n = (float)(SEQL * HD);
        float mean = S / n;
        float var  = Q / n - mean * mean;
        g_mean[b] = mean;
        g_rstd[b] = rsqrtf(var + LN_EPS);
    }
}

// ---------------- QKV projections (LN fused into the load) ----------------
// grid.x = b*NH+h, grid.y = {0:q, 1:k, 2:v}
#define XST 211
#define QKV_SMEM ((64 * XST + 64 * 68) * 4)
__global__ __launch_bounds__(256) void qkv_kernel(
    const float* __restrict__ lnw, const float* __restrict__ lnb,
    const float* __restrict__ Wq, const float* __restrict__ bq,
    const float* __restrict__ Wk, const float* __restrict__ bk,
    const float* __restrict__ Wv, const float* __restrict__ bv) {
    extern __shared__ float smem[];
    float* Xs = smem;             // [64][XST]  x normalized, d-major
    float* Wt = smem + 64 * XST;  // [64][68]   weight transposed, d-major

    int bh = blockIdx.x, b = bh / NH, h = bh % NH;
    int m = blockIdx.y;
    const float* W    = (m == 0 ? Wq : (m == 1 ? Wk : Wv)) + (size_t)h * DH * DH;
    const float* bias = (m == 0 ? bq : (m == 1 ? bk : bv)) + h * DH;
    float* outp = (m == 0 ? g_q : (m == 1 ? g_k : g_v)) + (size_t)bh * SEQL * DH;

    float mean = g_mean[b], rstd = g_rstd[b];
    const float* tb = g_tokens + (size_t)b * SEQL * HD + h * DH;

    for (int li = threadIdx.x; li < SEQL * 16; li += 256) {
        int s = li >> 4, d4 = (li & 15) * 4;
        float4 tv = *(const float4*)(tb + (size_t)s * HD + d4);
        float4 wv = *(const float4*)(lnw + (size_t)s * HD + h * DH + d4);
        float4 bb = *(const float4*)(lnb + (size_t)s * HD + h * DH + d4);
        Xs[(d4 + 0) * XST + s] = (tv.x - mean) * rstd * wv.x + bb.x;
        Xs[(d4 + 1) * XST + s] = (tv.y - mean) * rstd * wv.y + bb.y;
        Xs[(d4 + 2) * XST + s] = (tv.z - mean) * rstd * wv.z + bb.z;
        Xs[(d4 + 3) * XST + s] = (tv.w - mean) * rstd * wv.w + bb.w;
    }
    for (int li = threadIdx.x; li < 64 * 16; li += 256) {
        int e = li >> 4, d4 = (li & 15) * 4;
        float4 w4 = *(const float4*)(W + e * DH + d4);
        Wt[(d4 + 0) * 68 + e] = w4.x;
        Wt[(d4 + 1) * 68 + e] = w4.y;
        Wt[(d4 + 2) * 68 + e] = w4.z;
        Wt[(d4 + 3) * 68 + e] = w4.w;
    }
    __syncthreads();

    int tx = threadIdx.x & 15, ty = threadIdx.x >> 4;
    float acc[13][4] = {};
    for (int d = 0; d < 64; d++) {
        float4 w4 = *(const float4*)&Wt[d * 68 + tx * 4];
        const float* xr = &Xs[d * XST];
#pragma unroll
        for (int t = 0; t < 13; t++) {
            float xv = xr[ty + 16 * t];  // rows >=197 read garbage; stores guarded
            acc[t][0] += xv * w4.x;
            acc[t][1] += xv * w4.y;
            acc[t][2] += xv * w4.z;
            acc[t][3] += xv * w4.w;
        }
    }
    float4 b4 = *(const float4*)(bias + tx * 4);
#pragma unroll
    for (int t = 0; t < 13; t++) {
        int r = ty + 16 * t;
        if (r < SEQL) {
            float4 o = {acc[t][0] + b4.x, acc[t][1] + b4.y,
                        acc[t][2] + b4.z, acc[t][3] + b4.w};
            *(float4*)(outp + (size_t)r * DH + tx * 4) = o;
        }
    }
}

// ---------------- attention + residual (writes final output) ----------------
#define KS_FLOATS 12808  // 197*65 rounded up to multiple of 4 for float4 alignment of Vs
#define ATT_SMEM ((KS_FLOATS + SEQL * 64 + 8 * 64 + 8 * SEQL) * 4)
__global__ __launch_bounds__(256) void attn_kernel(float* __restrict__ out) {
    extern __shared__ float smem[];
    float* Ks = smem;                         // [197][65] (pad 65 -> conflict-free lane->t)
    float* Vs = smem + KS_FLOATS;             // [197][64]
    float* Qs = Vs + SEQL * 64;               // [8][64]
    float* Ps = Qs + 8 * 64;                  // [8][197]

    int bh = blockIdx.x, b = bh / NH, h = bh % NH;
    const float* kp = g_k + (size_t)bh * SEQL * DH;
    const float* vp = g_v + (size_t)bh * SEQL * DH;
    const float* qp = g_q + (size_t)bh * SEQL * DH;

    for (int li = threadIdx.x; li < SEQL * 16; li += 256) {
        int t = li >> 4, e4 = (li & 15) * 4;
        float4 kv = *(const float4*)(kp + (size_t)t * DH + e4);
        Ks[t * 65 + e4 + 0] = kv.x; Ks[t * 65 + e4 + 1] = kv.y;
        Ks[t * 65 + e4 + 2] = kv.z; Ks[t * 65 + e4 + 3] = kv.w;
        float4 vv = *(const float4*)(vp + (size_t)t * DH + e4);
        *(float4*)&Vs[t * 64 + e4] = vv;
    }
    __syncthreads();

    int w = threadIdx.x >> 5, l = threadIdx.x & 31;
    for (int s = w; s < SEQL; s += 8) {
        // stage q row, then spread to registers
        Qs[w * 64 + l]      = qp[(size_t)s * DH + l];
        Qs[w * 64 + l + 32] = qp[(size_t)s * DH + l + 32];
        __syncwarp();
        float q[64];
#pragma unroll
        for (int e4 = 0; e4 < 16; e4++) {
            float4 t4 = *(const float4*)&Qs[w * 64 + e4 * 4];
            q[e4 * 4 + 0] = t4.x; q[e4 * 4 + 1] = t4.y;
            q[e4 * 4 + 2] = t4.z; q[e4 * 4 + 3] = t4.w;
        }
        // scores: lane l handles t = l, l+32, ...
        float sc[7];
#pragma unroll
        for (int j = 0; j < 7; j++) {
            int t = l + 32 * j;
            if (t < SEQL) {
                const float* kr = &Ks[t * 65];
                float a = 0.f;
#pragma unroll
                for (int e = 0; e < 64; e++) a += q[e] * kr[e];
                sc[j] = a * 0.125f;  // 1/sqrt(64)
            } else sc[j] = -1e30f;
        }
        float mx = sc[0];
#pragma unroll
        for (int j = 1; j < 7; j++) mx = fmaxf(mx, sc[j]);
#pragma unroll
        for (int o = 16; o; o >>= 1) mx = fmaxf(mx, __shfl_xor_sync(0xffffffffu, mx, o));
        float ssum = 0.f;
#pragma unroll
        for (int j = 0; j < 7; j++) { sc[j] = expf(sc[j] - mx); ssum += sc[j]; }
#pragma unroll
        for (int o = 16; o; o >>= 1) ssum += __shfl_xor_sync(0xffffffffu, ssum, o);
        float inv = 1.0f / ssum;
#pragma unroll
        for (int j = 0; j < 7; j++) {
            int t = l + 32 * j;
            if (t < SEQL) Ps[w * SEQL + t] = sc[j] * inv;
        }
        __syncwarp();
        // AV: lane handles columns l and l+32
        float a0 = 0.f, a1 = 0.f;
        const float* pr = &Ps[w * SEQL];
#pragma unroll 4
        for (int t = 0; t < SEQL; t++) {
            float p = pr[t];
            a0 += p * Vs[t * 64 + l];
            a1 += p * Vs[t * 64 + l + 32];
        }
        size_t ob = ((size_t)b * SEQL + s) * HD + h * DH;
        out[ob + l]      = g_tokens[ob + l] + a0;
        out[ob + l + 32] = g_tokens[ob + l + 32] + a1;
        __syncwarp();
    }
}

// ---------------- launcher ----------------
extern "C" void kernel_launch(void* const* d_in, const int* in_sizes, int n_in,
                              void* d_out, int out_size) {
    const float* images = (const float*)d_in[0];
    const float* W_map  = (const float*)d_in[1];
    const float* b_map  = (const float*)d_in[2];
    const float* cls    = (const float*)d_in[3];
    const float* ln_w   = (const float*)d_in[4];
    const float* ln_b   = (const float*)d_in[5];
    const float* Wq     = (const float*)d_in[6];
    const float* bq     = (const float*)d_in[7];
    const float* Wk     = (const float*)d_in[8];
    const float* bk     = (const float*)d_in[9];
    const float* Wv     = (const float*)d_in[10];
    const float* bv     = (const float*)d_in[11];
    float* out = (float*)d_out;

    cudaFuncSetAttribute(gemm_tokens_mma, cudaFuncAttributeMaxDynamicSharedMemorySize, G_SMEM);
    cudaFuncSetAttribute(qkv_kernel,  cudaFuncAttributeMaxDynamicSharedMemorySize, QKV_SMEM);
    cudaFuncSetAttribute(attn_kernel, cudaFuncAttributeMaxDynamicSharedMemorySize, ATT_SMEM);

    pos_kernel<<<(SEQL * HD + 255) / 256, 256>>>();
    cls_kernel<<<NB, 256>>>(cls);
    gemm_tokens_mma<<<dim3((NB * NPAT) / 128, HD / 64), 256, G_SMEM>>>(images, W_map, b_map);
    stats_kernel<<<NB, 256>>>();
    qkv_kernel<<<dim3(NB * NH, 3), 256, QKV_SMEM>>>(ln_w, ln_b, Wq, bq, Wk, bk, Wv, bv);
    attn_kernel<<<NB * NH, 256, ATT_SMEM>>>(out);
}

// round 7
// speedup vs baseline: 2.1577x; 1.8138x over previous
#include <cuda_runtime.h>
#include <cuda_bf16.h>
#include <math.h>
#include <stdint.h>

#define NB   128
#define SEQL 197
#define NPAT 196
#define HD   768
#define NH   12
#define DH   64
#define LN_EPS 1e-5f

// ---------------- scratch (static device globals; no allocs) ----------------
static __device__ float g_tokens[NB * SEQL * HD];          // 77.4 MB
static __device__ float g_pos[SEQL * HD];
static __device__ float g_mean[NB];
static __device__ float g_rstd[NB];
static __device__ float g_q[NB * NH * SEQL * DH];          // [b][h][s][e]
static __device__ float g_k[NB * NH * SEQL * DH];
static __device__ float g_v[NB * NH * SEQL * DH];

// ================= helpers =================
__device__ __forceinline__ uint32_t smem_u32(const void* p) {
    uint32_t a;
    asm("{ .reg .u64 t; cvta.to.shared.u64 t, %1; cvt.u32.u64 %0, t; }" : "=r"(a) : "l"(p));
    return a;
}
#define LDSM4(r, addr) \
    asm volatile("ldmatrix.sync.aligned.m8n8.x4.shared.b16 {%0,%1,%2,%3}, [%4];" \
        : "=r"((r)[0]), "=r"((r)[1]), "=r"((r)[2]), "=r"((r)[3]) : "r"(addr))

__device__ __forceinline__ void mma_bf16(float* c, const uint32_t* a, const uint32_t* b) {
    asm volatile("mma.sync.aligned.m16n8k16.row.col.f32.bf16.bf16.f32 "
        "{%0,%1,%2,%3}, {%4,%5,%6,%7}, {%8,%9}, {%0,%1,%2,%3};"
        : "+f"(c[0]), "+f"(c[1]), "+f"(c[2]), "+f"(c[3])
        : "r"(a[0]), "r"(a[1]), "r"(a[2]), "r"(a[3]), "r"(b[0]), "r"(b[1]));
}

__device__ __forceinline__ uint32_t pack_bf16(__nv_bfloat16 x, __nv_bfloat16 y) {
    __nv_bfloat162 t = {x, y};
    return *(uint32_t*)&t;
}
__device__ __forceinline__ uint32_t pack_bf16_f(float x, float y) {
    return pack_bf16(__float2bfloat16(x), __float2bfloat16(y));
}

// ---------------- positional embeddings ----------------
__global__ void pos_kernel() {
    int idx = blockIdx.x * blockDim.x + threadIdx.x;
    if (idx >= SEQL * HD) return;
    int i = idx / HD, j = idx % HD;
    float jf = (float)(j & ~1);
    float denom = powf(10000.0f, jf / (float)HD);
    float arg = (float)i / denom;
    g_pos[idx] = (j & 1) ? cosf(arg) : sinf(arg);
}

// ---------------- class token row ----------------
__global__ void cls_kernel(const float* __restrict__ cls) {
    int b = blockIdx.x;
    for (int j = threadIdx.x; j < HD; j += blockDim.x)
        g_tokens[(size_t)b * SEQL * HD + j] = cls[j] + g_pos[j];
}

// ---------------- token projection GEMM via mma.sync bf16x3 ----------------
#define KS 72  // padded smem row stride (bf16 elems)
#define GA_H 0
#define GA_L (128 * KS)
#define GB_H (256 * KS)
#define GB_L (320 * KS)
#define G_SMEM (384 * KS * 2)

__global__ __launch_bounds__(256) void gemm_tokens_mma(const float* __restrict__ A,
                                                       const float* __restrict__ Wm,
                                                       const float* __restrict__ bias) {
    extern __shared__ char smc[];
    __nv_bfloat16* sm = (__nv_bfloat16*)smc;
    const int tid  = threadIdx.x;
    const int lane = tid & 31, wid = tid >> 5;
    const int wm = wid & 3, wn = wid >> 2;
    const int m0 = blockIdx.x * 128;
    const int n0 = blockIdx.y * 64;

    float c[2][4][4] = {};

    for (int kt = 0; kt < HD; kt += 64) {
#pragma unroll
        for (int it = 0; it < 8; it++) {
            int idx = tid + it * 256;
            int row = idx >> 4, c4 = (idx & 15) * 4;
            float4 v = *(const float4*)(A + (size_t)(m0 + row) * HD + kt + c4);
            __nv_bfloat16 hx = __float2bfloat16(v.x), hy = __float2bfloat16(v.y);
            __nv_bfloat16 hz = __float2bfloat16(v.z), hw = __float2bfloat16(v.w);
            uint2 hp = {pack_bf16(hx, hy), pack_bf16(hz, hw)};
            uint2 lp = {pack_bf16_f(v.x - __bfloat162float(hx), v.y - __bfloat162float(hy)),
                        pack_bf16_f(v.z - __bfloat162float(hz), v.w - __bfloat162float(hw))};
            *(uint2*)&sm[GA_H + row * KS + c4] = hp;
            *(uint2*)&sm[GA_L + row * KS + c4] = lp;
        }
#pragma unroll
        for (int it = 0; it < 4; it++) {
            int idx = tid + it * 256;
            int row = idx >> 4, c4 = (idx & 15) * 4;
            float4 v = *(const float4*)(Wm + (size_t)(n0 + row) * HD + kt + c4);
            __nv_bfloat16 hx = __float2bfloat16(v.x), hy = __float2bfloat16(v.y);
            __nv_bfloat16 hz = __float2bfloat16(v.z), hw = __float2bfloat16(v.w);
            uint2 hp = {pack_bf16(hx, hy), pack_bf16(hz, hw)};
            uint2 lp = {pack_bf16_f(v.x - __bfloat162float(hx), v.y - __bfloat162float(hy)),
                        pack_bf16_f(v.z - __bfloat162float(hz), v.w - __bfloat162float(hw))};
            *(uint2*)&sm[GB_H + row * KS + c4] = hp;
            *(uint2*)&sm[GB_L + row * KS + c4] = lp;
        }
        __syncthreads();

#pragma unroll
        for (int ks = 0; ks < 4; ks++) {
            const int k0 = ks * 16;
            uint32_t ah[2][4], al[2][4], bh[4][2], bl[4][2];
#pragma unroll
            for (int mf = 0; mf < 2; mf++) {
                int r = wm * 32 + mf * 16 + (lane & 15);
                int ko = k0 + (lane >> 4) * 8;
                LDSM4(ah[mf], smem_u32(&sm[GA_H + r * KS + ko]));
                LDSM4(al[mf], smem_u32(&sm[GA_L + r * KS + ko]));
            }
#pragma unroll
            for (int nf2 = 0; nf2 < 2; nf2++) {
                int seg = lane >> 3;
                int r = wn * 32 + nf2 * 16 + (seg >> 1) * 8 + (lane & 7);
                int ko = k0 + (seg & 1) * 8;
                uint32_t t4[4];
                LDSM4(t4, smem_u32(&sm[GB_H + r * KS + ko]));
                bh[nf2 * 2 + 0][0] = t4[0]; bh[nf2 * 2 + 0][1] = t4[1];
                bh[nf2 * 2 + 1][0] = t4[2]; bh[nf2 * 2 + 1][1] = t4[3];
                LDSM4(t4, smem_u32(&sm[GB_L + r * KS + ko]));
                bl[nf2 * 2 + 0][0] = t4[0]; bl[nf2 * 2 + 0][1] = t4[1];
                bl[nf2 * 2 + 1][0] = t4[2]; bl[nf2 * 2 + 1][1] = t4[3];
            }
#pragma unroll
            for (int mf = 0; mf < 2; mf++)
#pragma unroll
                for (int nf = 0; nf < 4; nf++) {
                    mma_bf16(c[mf][nf], ah[mf], bh[nf]);
                    mma_bf16(c[mf][nf], ah[mf], bl[nf]);
                    mma_bf16(c[mf][nf], al[mf], bh[nf]);
                }
        }
        __syncthreads();
    }

#pragma unroll
    for (int mf = 0; mf < 2; mf++) {
#pragma unroll
        for (int half = 0; half < 2; half++) {
            int mg = m0 + wm * 32 + mf * 16 + (lane >> 2) + half * 8;
            int b = mg / NPAT, p = mg % NPAT;
            float* orow = g_tokens + ((size_t)b * SEQL + p + 1) * HD;
            const float* prow = g_pos + (size_t)(p + 1) * HD;
#pragma unroll
            for (int nf = 0; nf < 4; nf++) {
                int col = n0 + wn * 32 + nf * 8 + (lane & 3) * 2;
                float2 o;
                o.x = c[mf][nf][half * 2 + 0] + bias[col] + prow[col];
                o.y = c[mf][nf][half * 2 + 1] + bias[col + 1] + prow[col + 1];
                *(float2*)(orow + col) = o;
            }
        }
    }
}

// ---------------- per-sample LN stats ----------------
__global__ __launch_bounds__(256) void stats_kernel() {
    int b = blockIdx.x;
    const float4* base = (const float4*)(g_tokens + (size_t)b * SEQL * HD);
    const int n4 = SEQL * HD / 4;
    float s = 0.f, sq = 0.f;
    for (int i = threadIdx.x; i < n4; i += 256) {
        float4 v = base[i];
        s  += v.x + v.y + v.z + v.w;
        sq += v.x * v.x + v.y * v.y + v.z * v.z + v.w * v.w;
    }
    __shared__ float sh[64];
#pragma unroll
    for (int o = 16; o; o >>= 1) {
        s  += __shfl_xor_sync(0xffffffffu, s, o);
        sq += __shfl_xor_sync(0xffffffffu, sq, o);
    }
    int w = threadIdx.x >> 5, l = threadIdx.x & 31;
    if (!l) { sh[w] = s; sh[32 + w] = sq; }
    __syncthreads();
    if (threadIdx.x == 0) {
        float S = 0.f, Q = 0.f;
        for (int i = 0; i < 8; i++) { S += sh[i]; Q += sh[32 + i]; }
        const float n = (float)(SEQL * HD);
        float mean = S / n;
        float var  = Q / n - mean * mean;
        g_mean[b] = mean;
        g_rstd[b] = rsqrtf(var + LN_EPS);
    }
}

// ---------------- QKV projections (LN fused into the load) ----------------
#define XST 211
#define QKV_SMEM ((64 * XST + 64 * 68) * 4)
__global__ __launch_bounds__(256) void qkv_kernel(
    const float* __restrict__ lnw, const float* __restrict__ lnb,
    const float* __restrict__ Wq, const float* __restrict__ bq,
    const float* __restrict__ Wk, const float* __restrict__ bk,
    const float* __restrict__ Wv, const float* __restrict__ bv) {
    extern __shared__ float smem[];
    float* Xs = smem;
    float* Wt = smem + 64 * XST;

    int bh = blockIdx.x, b = bh / NH, h = bh % NH;
    int m = blockIdx.y;
    const float* W    = (m == 0 ? Wq : (m == 1 ? Wk : Wv)) + (size_t)h * DH * DH;
    const float* bias = (m == 0 ? bq : (m == 1 ? bk : bv)) + h * DH;
    float* outp = (m == 0 ? g_q : (m == 1 ? g_k : g_v)) + (size_t)bh * SEQL * DH;

    float mean = g_mean[b], rstd = g_rstd[b];
    const float* tb = g_tokens + (size_t)b * SEQL * HD + h * DH;

    for (int li = threadIdx.x; li < SEQL * 16; li += 256) {
        int s = li >> 4, d4 = (li & 15) * 4;
        float4 tv = *(const float4*)(tb + (size_t)s * HD + d4);
        float4 wv = *(const float4*)(lnw + (size_t)s * HD + h * DH + d4);
        float4 bb = *(const float4*)(lnb + (size_t)s * HD + h * DH + d4);
        Xs[(d4 + 0) * XST + s] = (tv.x - mean) * rstd * wv.x + bb.x;
        Xs[(d4 + 1) * XST + s] = (tv.y - mean) * rstd * wv.y + bb.y;
        Xs[(d4 + 2) * XST + s] = (tv.z - mean) * rstd * wv.z + bb.z;
        Xs[(d4 + 3) * XST + s] = (tv.w - mean) * rstd * wv.w + bb.w;
    }
    for (int li = threadIdx.x; li < 64 * 16; li += 256) {
        int e = li >> 4, d4 = (li & 15) * 4;
        float4 w4 = *(const float4*)(W + e * DH + d4);
        Wt[(d4 + 0) * 68 + e] = w4.x;
        Wt[(d4 + 1) * 68 + e] = w4.y;
        Wt[(d4 + 2) * 68 + e] = w4.z;
        Wt[(d4 + 3) * 68 + e] = w4.w;
    }
    __syncthreads();

    int tx = threadIdx.x & 15, ty = threadIdx.x >> 4;
    float acc[13][4] = {};
    for (int d = 0; d < 64; d++) {
        float4 w4 = *(const float4*)&Wt[d * 68 + tx * 4];
        const float* xr = &Xs[d * XST];
#pragma unroll
        for (int t = 0; t < 13; t++) {
            float xv = xr[ty + 16 * t];
            acc[t][0] += xv * w4.x;
            acc[t][1] += xv * w4.y;
            acc[t][2] += xv * w4.z;
            acc[t][3] += xv * w4.w;
        }
    }
    float4 b4 = *(const float4*)(bias + tx * 4);
#pragma unroll
    for (int t = 0; t < 13; t++) {
        int r = ty + 16 * t;
        if (r < SEQL) {
            float4 o = {acc[t][0] + b4.x, acc[t][1] + b4.y,
                        acc[t][2] + b4.z, acc[t][3] + b4.w};
            *(float4*)(outp + (size_t)r * DH + tx * 4) = o;
        }
    }
}

// ---------------- attention via mma.sync (flash-style, registers) ----------------
// One CTA (8 warps) per (b,h). SEQ padded 197->208 (13 m16 tiles).
// smem: K bf16 [208][72], Q bf16 [208][72] (pre-scaled 1/8), Vt bf16 [64][216].
#define SEQP 208
#define KQS  72
#define VTS  216
#define AOFF_K  0
#define AOFF_Q  (SEQP * KQS)
#define AOFF_VT (2 * SEQP * KQS)
#define ATT2_SMEM ((2 * SEQP * KQS + 64 * VTS) * 2)

__global__ void __launch_bounds__(256, 1) attn_mma(float* __restrict__ out) {
    extern __shared__ __nv_bfloat16 asm_[];
    const int tid = threadIdx.x, lane = tid & 31, w = tid >> 5;
    const int bh = blockIdx.x, b = bh / NH, h = bh % NH;
    const float* qp = g_q + (size_t)bh * SEQL * DH;
    const float* kp = g_k + (size_t)bh * SEQL * DH;
    const float* vp = g_v + (size_t)bh * SEQL * DH;

    // stage K and Q (scaled), zero-padded rows
    for (int idx = tid; idx < SEQP * 16; idx += 256) {
        int t = idx >> 4, e4 = (idx & 15) * 4;
        float4 kv = {0.f, 0.f, 0.f, 0.f}, qv = {0.f, 0.f, 0.f, 0.f};
        if (t < SEQL) {
            kv = *(const float4*)(kp + (size_t)t * DH + e4);
            qv = *(const float4*)(qp + (size_t)t * DH + e4);
        }
        uint2 kpq = {pack_bf16_f(kv.x, kv.y), pack_bf16_f(kv.z, kv.w)};
        uint2 qpq = {pack_bf16_f(qv.x * 0.125f, qv.y * 0.125f),
                     pack_bf16_f(qv.z * 0.125f, qv.w * 0.125f)};
        *(uint2*)&asm_[AOFF_K + t * KQS + e4] = kpq;
        *(uint2*)&asm_[AOFF_Q + t * KQS + e4] = qpq;
    }
    // Vt: zero tail cols 197..207, then transpose-store V
    for (int idx = tid; idx < 64 * 11; idx += 256) {
        int e = idx / 11, t = SEQL + idx % 11;
        asm_[AOFF_VT + e * VTS + t] = __float2bfloat16(0.f);
    }
    for (int idx = tid; idx < SEQL * 16; idx += 256) {
        int t = idx >> 4, e4 = (idx & 15) * 4;
        float4 v = *(const float4*)(vp + (size_t)t * DH + e4);
        asm_[AOFF_VT + (e4 + 0) * VTS + t] = __float2bfloat16(v.x);
        asm_[AOFF_VT + (e4 + 1) * VTS + t] = __float2bfloat16(v.y);
        asm_[AOFF_VT + (e4 + 2) * VTS + t] = __float2bfloat16(v.z);
        asm_[AOFF_VT + (e4 + 3) * VTS + t] = __float2bfloat16(v.w);
    }
    __syncthreads();

    const int seg = lane >> 3;
    for (int mt = w; mt < 13; mt += 8) {
        float c[26][4];
#pragma unroll
        for (int nf = 0; nf < 26; nf++)
            c[nf][0] = c[nf][1] = c[nf][2] = c[nf][3] = 0.f;

        // S = Qs * K^T
#pragma unroll
        for (int ksx = 0; ksx < 4; ksx++) {
            uint32_t a[4];
            {
                int r = mt * 16 + (lane & 15);
                int co = ksx * 16 + (lane >> 4) * 8;
                LDSM4(a, smem_u32(&asm_[AOFF_Q + r * KQS + co]));
            }
#pragma unroll
            for (int nf2 = 0; nf2 < 13; nf2++) {
                int r = nf2 * 16 + (seg >> 1) * 8 + (lane & 7);
                int co = ksx * 16 + (seg & 1) * 8;
                uint32_t t4[4];
                LDSM4(t4, smem_u32(&asm_[AOFF_K + r * KQS + co]));
                mma_bf16(c[2 * nf2 + 0], a, t4 + 0);
                mma_bf16(c[2 * nf2 + 1], a, t4 + 2);
            }
        }

        // mask padded columns (cols >= 197)
        {
            int cb = (lane & 3) * 2;
            if (192 + cb >= SEQL) { c[24][0] = -1e30f; c[24][2] = -1e30f; }
            if (193 + cb >= SEQL) { c[24][1] = -1e30f; c[24][3] = -1e30f; }
            c[25][0] = c[25][1] = c[25][2] = c[25][3] = -1e30f;
        }

        // softmax over registers (rows r0 = lane>>2 and r0+8)
        float mx0 = -1e30f, mx1 = -1e30f;
#pragma unroll
        for (int nf = 0; nf < 26; nf++) {
            mx0 = fmaxf(mx0, fmaxf(c[nf][0], c[nf][1]));
            mx1 = fmaxf(mx1, fmaxf(c[nf][2], c[nf][3]));
        }
        mx0 = fmaxf(mx0, __shfl_xor_sync(0xffffffffu, mx0, 1));
        mx0 = fmaxf(mx0, __shfl_xor_sync(0xffffffffu, mx0, 2));
        mx1 = fmaxf(mx1, __shfl_xor_sync(0xffffffffu, mx1, 1));
        mx1 = fmaxf(mx1, __shfl_xor_sync(0xffffffffu, mx1, 2));
        float s0 = 0.f, s1 = 0.f;
#pragma unroll
        for (int nf = 0; nf < 26; nf++) {
            c[nf][0] = __expf(c[nf][0] - mx0); s0 += c[nf][0];
            c[nf][1] = __expf(c[nf][1] - mx0); s0 += c[nf][1];
            c[nf][2] = __expf(c[nf][2] - mx1); s1 += c[nf][2];
            c[nf][3] = __expf(c[nf][3] - mx1); s1 += c[nf][3];
        }
        s0 += __shfl_xor_sync(0xffffffffu, s0, 1);
        s0 += __shfl_xor_sync(0xffffffffu, s0, 2);
        s1 += __shfl_xor_sync(0xffffffffu, s1, 1);
        s1 += __shfl_xor_sync(0xffffffffu, s1, 2);
        float inv0 = 1.0f / s0, inv1 = 1.0f / s1;

        // O = P * V^T (P from register relayout of C-frags)
        float o[8][4];
#pragma unroll
        for (int ne = 0; ne < 8; ne++)
            o[ne][0] = o[ne][1] = o[ne][2] = o[ne][3] = 0.f;

#pragma unroll
        for (int kt = 0; kt < 13; kt++) {
            uint32_t pa[4];
            pa[0] = pack_bf16_f(c[2 * kt][0] * inv0, c[2 * kt][1] * inv0);
            pa[1] = pack_bf16_f(c[2 * kt][2] * inv1, c[2 * kt][3] * inv1);
            pa[2] = pack_bf16_f(c[2 * kt + 1][0] * inv0, c[2 * kt + 1][1] * inv0);
            pa[3] = pack_bf16_f(c[2 * kt + 1][2] * inv1, c[2 * kt + 1][3] * inv1);
#pragma unroll
            for (int ne2 = 0; ne2 < 4; ne2++) {
                int r = ne2 * 16 + (seg >> 1) * 8 + (lane & 7);
                int co = kt * 16 + (seg & 1) * 8;
                uint32_t t4[4];
                LDSM4(t4, smem_u32(&asm_[AOFF_VT + r * VTS + co]));
                mma_bf16(o[2 * ne2 + 0], pa, t4 + 0);
                mma_bf16(o[2 * ne2 + 1], pa, t4 + 2);
            }
        }

        // epilogue: residual add, guarded stores
        int r0 = mt * 16 + (lane >> 2);
        int cb = (lane & 3) * 2;
        if (r0 < SEQL) {
            size_t base = ((size_t)b * SEQL + r0) * HD + h * DH;
#pragma unroll
            for (int ne = 0; ne < 8; ne++) {
                int n = ne * 8 + cb;
                float2 t = *(const float2*)(g_tokens + base + n);
                float2 ov = {t.x + o[ne][0], t.y + o[ne][1]};
                *(float2*)(out + base + n) = ov;
            }
        }
        if (r0 + 8 < SEQL) {
            size_t base = ((size_t)b * SEQL + r0 + 8) * HD + h * DH;
#pragma unroll
            for (int ne = 0; ne < 8; ne++) {
                int n = ne * 8 + cb;
                float2 t = *(const float2*)(g_tokens + base + n);
                float2 ov = {t.x + o[ne][2], t.y + o[ne][3]};
                *(float2*)(out + base + n) = ov;
            }
        }
    }
}

// ---------------- launcher ----------------
extern "C" void kernel_launch(void* const* d_in, const int* in_sizes, int n_in,
                              void* d_out, int out_size) {
    const float* images = (const float*)d_in[0];
    const float* W_map  = (const float*)d_in[1];
    const float* b_map  = (const float*)d_in[2];
    const float* cls    = (const float*)d_in[3];
    const float* ln_w   = (const float*)d_in[4];
    const float* ln_b   = (const float*)d_in[5];
    const float* Wq     = (const float*)d_in[6];
    const float* bq     = (const float*)d_in[7];
    const float* Wk     = (const float*)d_in[8];
    const float* bk     = (const float*)d_in[9];
    const float* Wv     = (const float*)d_in[10];
    const float* bv     = (const float*)d_in[11];
    float* out = (float*)d_out;

    cudaFuncSetAttribute(gemm_tokens_mma, cudaFuncAttributeMaxDynamicSharedMemorySize, G_SMEM);
    cudaFuncSetAttribute(qkv_kernel,  cudaFuncAttributeMaxDynamicSharedMemorySize, QKV_SMEM);
    cudaFuncSetAttribute(attn_mma, cudaFuncAttributeMaxDynamicSharedMemorySize, ATT2_SMEM);

    pos_kernel<<<(SEQL * HD + 255) / 256, 256>>>();
    cls_kernel<<<NB, 256>>>(cls);
    gemm_tokens_mma<<<dim3((NB * NPAT) / 128, HD / 64), 256, G_SMEM>>>(images, W_map, b_map);
    stats_kernel<<<NB, 256>>>();
    qkv_kernel<<<dim3(NB * NH, 3), 256, QKV_SMEM>>>(ln_w, ln_b, Wq, bq, Wk, bk, Wv, bv);
    attn_mma<<<NB * NH, 256, ATT2_SMEM>>>(out);
}

// round 8
// speedup vs baseline: 3.2623x; 1.5119x over previous
#include <cuda_runtime.h>
#include <cuda_bf16.h>
#include <math.h>
#include <stdint.h>

#define NB   128
#define SEQL 197
#define NPAT 196
#define HD   768
#define NH   12
#define DH   64
#define LN_EPS 1e-5f

// ---------------- scratch (static device globals; no allocs) ----------------
static __device__ float g_tokens[NB * SEQL * HD];          // 77.4 MB
static __device__ float g_pos[SEQL * HD];
static __device__ float g_mean[NB];
static __device__ float g_rstd[NB];
static __device__ __nv_bfloat16 g_qb[NB * NH * SEQL * DH]; // bf16, q pre-scaled 1/8
static __device__ __nv_bfloat16 g_kb[NB * NH * SEQL * DH];
static __device__ __nv_bfloat16 g_vb[NB * NH * SEQL * DH];

// ================= helpers =================
__device__ __forceinline__ uint32_t smem_u32(const void* p) {
    uint32_t a;
    asm("{ .reg .u64 t; cvta.to.shared.u64 t, %1; cvt.u32.u64 %0, t; }" : "=r"(a) : "l"(p));
    return a;
}
#define LDSM4(r, addr) \
    asm volatile("ldmatrix.sync.aligned.m8n8.x4.shared.b16 {%0,%1,%2,%3}, [%4];" \
        : "=r"((r)[0]), "=r"((r)[1]), "=r"((r)[2]), "=r"((r)[3]) : "r"(addr))

__device__ __forceinline__ void mma_bf16(float* c, const uint32_t* a, const uint32_t* b) {
    asm volatile("mma.sync.aligned.m16n8k16.row.col.f32.bf16.bf16.f32 "
        "{%0,%1,%2,%3}, {%4,%5,%6,%7}, {%8,%9}, {%0,%1,%2,%3};"
        : "+f"(c[0]), "+f"(c[1]), "+f"(c[2]), "+f"(c[3])
        : "r"(a[0]), "r"(a[1]), "r"(a[2]), "r"(a[3]), "r"(b[0]), "r"(b[1]));
}

__device__ __forceinline__ uint32_t pack_bf16(__nv_bfloat16 x, __nv_bfloat16 y) {
    __nv_bfloat162 t = {x, y};
    return *(uint32_t*)&t;
}
__device__ __forceinline__ uint32_t pack_bf16_f(float x, float y) {
    return pack_bf16(__float2bfloat16(x), __float2bfloat16(y));
}
// hi/lo split of a float4 into packed bf16 pairs
__device__ __forceinline__ void split_f4(float4 v, uint2* hp, uint2* lp) {
    __nv_bfloat16 hx = __float2bfloat16(v.x), hy = __float2bfloat16(v.y);
    __nv_bfloat16 hz = __float2bfloat16(v.z), hw = __float2bfloat16(v.w);
    hp->x = pack_bf16(hx, hy); hp->y = pack_bf16(hz, hw);
    lp->x = pack_bf16_f(v.x - __bfloat162float(hx), v.y - __bfloat162float(hy));
    lp->y = pack_bf16_f(v.z - __bfloat162float(hz), v.w - __bfloat162float(hw));
}

// ---------------- positional embeddings ----------------
__global__ void pos_kernel() {
    int idx = blockIdx.x * blockDim.x + threadIdx.x;
    if (idx >= SEQL * HD) return;
    int i = idx / HD, j = idx % HD;
    float jf = (float)(j & ~1);
    float denom = powf(10000.0f, jf / (float)HD);
    float arg = (float)i / denom;
    g_pos[idx] = (j & 1) ? cosf(arg) : sinf(arg);
}

// ---------------- class token row ----------------
__global__ void cls_kernel(const float* __restrict__ cls) {
    int b = blockIdx.x;
    for (int j = threadIdx.x; j < HD; j += blockDim.x)
        g_tokens[(size_t)b * SEQL * HD + j] = cls[j] + g_pos[j];
}

// ---------------- token projection GEMM via mma.sync bf16x3 ----------------
// C[m,n] = sum_k A[m,k]*W[n,k]; M=25088, N=768, K=768.
// CTA tile 128x128, BK=64, 8 warps (4m x 2n), warp tile 32x64.
#define KS 72
#define GA_H 0
#define GA_L (128 * KS)
#define GB_H (256 * KS)
#define GB_L (384 * KS)
#define G_SMEM (512 * KS * 2)

__global__ __launch_bounds__(256) void gemm_tokens_mma(const float* __restrict__ A,
                                                       const float* __restrict__ Wm,
                                                       const float* __restrict__ bias) {
    extern __shared__ char smc[];
    __nv_bfloat16* sm = (__nv_bfloat16*)smc;
    const int tid  = threadIdx.x;
    const int lane = tid & 31, wid = tid >> 5;
    const int wm = wid & 3, wn = wid >> 2;
    const int seg = lane >> 3;
    const int n0 = blockIdx.x * 128;
    const int m0 = blockIdx.y * 128;

    float c[2][8][4] = {};

    for (int kt = 0; kt < HD; kt += 64) {
#pragma unroll
        for (int it = 0; it < 8; it++) {
            int idx = tid + it * 256;
            int row = idx >> 4, c4 = (idx & 15) * 4;
            float4 v = *(const float4*)(A + (size_t)(m0 + row) * HD + kt + c4);
            uint2 hp, lp;
            split_f4(v, &hp, &lp);
            *(uint2*)&sm[GA_H + row * KS + c4] = hp;
            *(uint2*)&sm[GA_L + row * KS + c4] = lp;
        }
#pragma unroll
        for (int it = 0; it < 8; it++) {
            int idx = tid + it * 256;
            int row = idx >> 4, c4 = (idx & 15) * 4;
            float4 v = *(const float4*)(Wm + (size_t)(n0 + row) * HD + kt + c4);
            uint2 hp, lp;
            split_f4(v, &hp, &lp);
            *(uint2*)&sm[GB_H + row * KS + c4] = hp;
            *(uint2*)&sm[GB_L + row * KS + c4] = lp;
        }
        __syncthreads();

#pragma unroll
        for (int ks = 0; ks < 4; ks++) {
            const int k0 = ks * 16;
            uint32_t ah[2][4], al[2][4];
#pragma unroll
            for (int mf = 0; mf < 2; mf++) {
                int r = wm * 32 + mf * 16 + (lane & 15);
                int ko = k0 + (lane >> 4) * 8;
                LDSM4(ah[mf], smem_u32(&sm[GA_H + r * KS + ko]));
                LDSM4(al[mf], smem_u32(&sm[GA_L + r * KS + ko]));
            }
#pragma unroll
            for (int nf2 = 0; nf2 < 4; nf2++) {
                int r = wn * 64 + nf2 * 16 + (seg >> 1) * 8 + (lane & 7);
                int ko = k0 + (seg & 1) * 8;
                uint32_t bh[4], bl[4];
                LDSM4(bh, smem_u32(&sm[GB_H + r * KS + ko]));
                LDSM4(bl, smem_u32(&sm[GB_L + r * KS + ko]));
#pragma unroll
                for (int mf = 0; mf < 2; mf++) {
                    mma_bf16(c[mf][nf2 * 2 + 0], ah[mf], bh + 0);
                    mma_bf16(c[mf][nf2 * 2 + 0], ah[mf], bl + 0);
                    mma_bf16(c[mf][nf2 * 2 + 0], al[mf], bh + 0);
                    mma_bf16(c[mf][nf2 * 2 + 1], ah[mf], bh + 2);
                    mma_bf16(c[mf][nf2 * 2 + 1], ah[mf], bl + 2);
                    mma_bf16(c[mf][nf2 * 2 + 1], al[mf], bh + 2);
                }
            }
        }
        __syncthreads();
    }

#pragma unroll
    for (int mf = 0; mf < 2; mf++) {
#pragma unroll
        for (int half = 0; half < 2; half++) {
            int mg = m0 + wm * 32 + mf * 16 + (lane >> 2) + half * 8;
            int b = mg / NPAT, p = mg % NPAT;
            float* orow = g_tokens + ((size_t)b * SEQL + p + 1) * HD;
            const float* prow = g_pos + (size_t)(p + 1) * HD;
#pragma unroll
            for (int nf = 0; nf < 8; nf++) {
                int col = n0 + wn * 64 + nf * 8 + (lane & 3) * 2;
                float2 o;
                o.x = c[mf][nf][half * 2 + 0] + bias[col] + prow[col];
                o.y = c[mf][nf][half * 2 + 1] + bias[col + 1] + prow[col + 1];
                *(float2*)(orow + col) = o;
            }
        }
    }
}

// ---------------- per-sample LN stats (1024 threads for MLP) ----------------
__global__ __launch_bounds__(1024) void stats_kernel() {
    int b = blockIdx.x;
    const float4* base = (const float4*)(g_tokens + (size_t)b * SEQL * HD);
    const int n4 = SEQL * HD / 4;
    float s = 0.f, sq = 0.f;
    for (int i = threadIdx.x; i < n4; i += 1024) {
        float4 v = base[i];
        s  += v.x + v.y + v.z + v.w;
        sq += v.x * v.x + v.y * v.y + v.z * v.z + v.w * v.w;
    }
    __shared__ float sh[64];
#pragma unroll
    for (int o = 16; o; o >>= 1) {
        s  += __shfl_xor_sync(0xffffffffu, s, o);
        sq += __shfl_xor_sync(0xffffffffu, sq, o);
    }
    int w = threadIdx.x >> 5, l = threadIdx.x & 31;
    if (!l) { sh[w] = s; sh[32 + w] = sq; }
    __syncthreads();
    if (threadIdx.x == 0) {
        float S = 0.f, Q = 0.f;
        for (int i = 0; i < 32; i++) { S += sh[i]; Q += sh[32 + i]; }
        const float n = (float)(SEQL * HD);
        float mean = S / n;
        float var  = Q / n - mean * mean;
        g_mean[b] = mean;
        g_rstd[b] = rsqrtf(var + LN_EPS);
    }
}

// ---------------- QKV projections via mma.sync (LN fused, bf16 out) ----------------
// One CTA per (b,h): X_norm [197x64] once, q/k/v = X*W^T + b, bf16 outputs.
#define SEQP 208
#define QKS  72
#define QX_H 0
#define QX_L (SEQP * QKS)
#define QW_H (2 * SEQP * QKS)
#define QW_L (2 * SEQP * QKS + 3 * 64 * QKS)
#define QKV2_SMEM ((2 * SEQP * QKS + 6 * 64 * QKS) * 2)

__global__ void __launch_bounds__(256, 1) qkv_mma(
    const float* __restrict__ lnw, const float* __restrict__ lnb,
    const float* __restrict__ Wq, const float* __restrict__ bq,
    const float* __restrict__ Wk, const float* __restrict__ bk,
    const float* __restrict__ Wv, const float* __restrict__ bv) {
    extern __shared__ __nv_bfloat16 qsm[];
    const int tid = threadIdx.x, lane = tid & 31, w = tid >> 5;
    const int seg = lane >> 3;
    const int bh = blockIdx.x, b = bh / NH, h = bh % NH;
    const float mean = g_mean[b], rstd = g_rstd[b];
    const float* tb = g_tokens + (size_t)b * SEQL * HD + h * DH;

    // stage X normalized (hi/lo), zero-padded rows
    for (int idx = tid; idx < SEQP * 16; idx += 256) {
        int s = idx >> 4, d4 = (idx & 15) * 4;
        float4 x = {0.f, 0.f, 0.f, 0.f};
        if (s < SEQL) {
            float4 tv = *(const float4*)(tb + (size_t)s * HD + d4);
            float4 wv = *(const float4*)(lnw + (size_t)s * HD + h * DH + d4);
            float4 bb = *(const float4*)(lnb + (size_t)s * HD + h * DH + d4);
            x.x = (tv.x - mean) * rstd * wv.x + bb.x;
            x.y = (tv.y - mean) * rstd * wv.y + bb.y;
            x.z = (tv.z - mean) * rstd * wv.z + bb.z;
            x.w = (tv.w - mean) * rstd * wv.w + bb.w;
        }
        uint2 hp, lp;
        split_f4(x, &hp, &lp);
        *(uint2*)&qsm[QX_H + s * QKS + d4] = hp;
        *(uint2*)&qsm[QX_L + s * QKS + d4] = lp;
    }
    // stage W (3x 64x64, hi/lo), row = e, col = d
    for (int idx = tid; idx < 3 * 64 * 16; idx += 256) {
        int m = idx >> 10, rem = idx & 1023;
        int e = rem >> 4, d4 = (rem & 15) * 4;
        const float* Wsrc = (m == 0 ? Wq : (m == 1 ? Wk : Wv)) + (size_t)h * DH * DH;
        float4 v = *(const float4*)(Wsrc + e * DH + d4);
        uint2 hp, lp;
        split_f4(v, &hp, &lp);
        *(uint2*)&qsm[QW_H + (m * 64 + e) * QKS + d4] = hp;
        *(uint2*)&qsm[QW_L + (m * 64 + e) * QKS + d4] = lp;
    }
    __syncthreads();

    // 39 tasks: (mt 0..12) x (m 0..2)
    for (int t = w; t < 39; t += 8) {
        const int mt = t / 3, m = t % 3;
        float c[8][4] = {};
#pragma unroll
        for (int ks = 0; ks < 4; ks++) {
            const int k0 = ks * 16;
            uint32_t ah[4], al[4];
            {
                int r = mt * 16 + (lane & 15);
                int ko = k0 + (lane >> 4) * 8;
                LDSM4(ah, smem_u32(&qsm[QX_H + r * QKS + ko]));
                LDSM4(al, smem_u32(&qsm[QX_L + r * QKS + ko]));
            }
#pragma unroll
            for (int nf2 = 0; nf2 < 4; nf2++) {
                int r = m * 64 + nf2 * 16 + (seg >> 1) * 8 + (lane & 7);
                int ko = k0 + (seg & 1) * 8;
                uint32_t bh2[4], bl2[4];
                LDSM4(bh2, smem_u32(&qsm[QW_H + r * QKS + ko]));
                LDSM4(bl2, smem_u32(&qsm[QW_L + r * QKS + ko]));
                mma_bf16(c[nf2 * 2 + 0], ah, bh2 + 0);
                mma_bf16(c[nf2 * 2 + 0], ah, bl2 + 0);
                mma_bf16(c[nf2 * 2 + 0], al, bh2 + 0);
                mma_bf16(c[nf2 * 2 + 1], ah, bh2 + 2);
                mma_bf16(c[nf2 * 2 + 1], ah, bl2 + 2);
                mma_bf16(c[nf2 * 2 + 1], al, bh2 + 2);
            }
        }
        // epilogue: + bias, (q: *0.125), bf16 store
        const float* bias = (m == 0 ? bq : (m == 1 ? bk : bv)) + h * DH;
        __nv_bfloat16* outp = (m == 0 ? g_qb : (m == 1 ? g_kb : g_vb)) + (size_t)bh * SEQL * DH;
        const float scale = (m == 0) ? 0.125f : 1.0f;
        int r0 = mt * 16 + (lane >> 2);
#pragma unroll
        for (int half = 0; half < 2; half++) {
            int r = r0 + half * 8;
            if (r < SEQL) {
#pragma unroll
                for (int nf = 0; nf < 8; nf++) {
                    int e = nf * 8 + (lane & 3) * 2;
                    float v0 = (c[nf][half * 2 + 0] + bias[e]) * scale;
                    float v1 = (c[nf][half * 2 + 1] + bias[e + 1]) * scale;
                    *(uint32_t*)&outp[(size_t)r * DH + e] = pack_bf16_f(v0, v1);
                }
            }
        }
    }
}

// ---------------- attention via mma.sync (flash-style, registers) ----------------
#define KQS  72
#define VTS  216
#define AOFF_K  0
#define AOFF_Q  (SEQP * KQS)
#define AOFF_VT (2 * SEQP * KQS)
#define ATT2_SMEM ((2 * SEQP * KQS + 64 * VTS) * 2)

__global__ void __launch_bounds__(256, 1) attn_mma(float* __restrict__ out) {
    extern __shared__ __nv_bfloat16 asm_[];
    const int tid = threadIdx.x, lane = tid & 31, w = tid >> 5;
    const int bh = blockIdx.x, b = bh / NH, h = bh % NH;
    const __nv_bfloat16* qp = g_qb + (size_t)bh * SEQL * DH;
    const __nv_bfloat16* kp = g_kb + (size_t)bh * SEQL * DH;
    const __nv_bfloat16* vp = g_vb + (size_t)bh * SEQL * DH;

    // stage K and Q (bf16 direct), zero-padded rows
    for (int idx = tid; idx < SEQP * 8; idx += 256) {
        int t = idx >> 3, e8 = (idx & 7) * 8;
        uint4 kv = {0u, 0u, 0u, 0u}, qv = {0u, 0u, 0u, 0u};
        if (t < SEQL) {
            kv = *(const uint4*)(kp + (size_t)t * DH + e8);
            qv = *(const uint4*)(qp + (size_t)t * DH + e8);
        }
        *(uint4*)&asm_[AOFF_K + t * KQS + e8] = kv;
        *(uint4*)&asm_[AOFF_Q + t * KQS + e8] = qv;
    }
    // Vt: zero tail cols, then transpose-store V
    for (int idx = tid; idx < 64 * 11; idx += 256) {
        int e = idx / 11, t = SEQL + idx % 11;
        asm_[AOFF_VT + e * VTS + t] = __float2bfloat16(0.f);
    }
    for (int idx = tid; idx < SEQL * 8; idx += 256) {
        int t = idx >> 3, e8 = (idx & 7) * 8;
        uint4 v = *(const uint4*)(vp + (size_t)t * DH + e8);
        __nv_bfloat162 p0 = *(__nv_bfloat162*)&v.x;
        __nv_bfloat162 p1 = *(__nv_bfloat162*)&v.y;
        __nv_bfloat162 p2 = *(__nv_bfloat162*)&v.z;
        __nv_bfloat162 p3 = *(__nv_bfloat162*)&v.w;
        asm_[AOFF_VT + (e8 + 0) * VTS + t] = p0.x;
        asm_[AOFF_VT + (e8 + 1) * VTS + t] = p0.y;
        asm_[AOFF_VT + (e8 + 2) * VTS + t] = p1.x;
        asm_[AOFF_VT + (e8 + 3) * VTS + t] = p1.y;
        asm_[AOFF_VT + (e8 + 4) * VTS + t] = p2.x;
        asm_[AOFF_VT + (e8 + 5) * VTS + t] = p2.y;
        asm_[AOFF_VT + (e8 + 6) * VTS + t] = p3.x;
        asm_[AOFF_VT + (e8 + 7) * VTS + t] = p3.y;
    }
    __syncthreads();

    const int seg = lane >> 3;
    for (int mt = w; mt < 13; mt += 8) {
        float c[26][4];
#pragma unroll
        for (int nf = 0; nf < 26; nf++)
            c[nf][0] = c[nf][1] = c[nf][2] = c[nf][3] = 0.f;

        // S = Qs * K^T
#pragma unroll
        for (int ksx = 0; ksx < 4; ksx++) {
            uint32_t a[4];
            {
                int r = mt * 16 + (lane & 15);
                int co = ksx * 16 + (lane >> 4) * 8;
                LDSM4(a, smem_u32(&asm_[AOFF_Q + r * KQS + co]));
            }
#pragma unroll
            for (int nf2 = 0; nf2 < 13; nf2++) {
                int r = nf2 * 16 + (seg >> 1) * 8 + (lane & 7);
                int co = ksx * 16 + (seg & 1) * 8;
                uint32_t t4[4];
                LDSM4(t4, smem_u32(&asm_[AOFF_K + r * KQS + co]));
                mma_bf16(c[2 * nf2 + 0], a, t4 + 0);
                mma_bf16(c[2 * nf2 + 1], a, t4 + 2);
            }
        }

        // mask padded columns (cols >= 197)
        {
            int cb = (lane & 3) * 2;
            if (192 + cb >= SEQL) { c[24][0] = -1e30f; c[24][2] = -1e30f; }
            if (193 + cb >= SEQL) { c[24][1] = -1e30f; c[24][3] = -1e30f; }
            c[25][0] = c[25][1] = c[25][2] = c[25][3] = -1e30f;
        }

        // softmax over registers
        float mx0 = -1e30f, mx1 = -1e30f;
#pragma unroll
        for (int nf = 0; nf < 26; nf++) {
            mx0 = fmaxf(mx0, fmaxf(c[nf][0], c[nf][1]));
            mx1 = fmaxf(mx1, fmaxf(c[nf][2], c[nf][3]));
        }
        mx0 = fmaxf(mx0, __shfl_xor_sync(0xffffffffu, mx0, 1));
        mx0 = fmaxf(mx0, __shfl_xor_sync(0xffffffffu, mx0, 2));
        mx1 = fmaxf(mx1, __shfl_xor_sync(0xffffffffu, mx1, 1));
        mx1 = fmaxf(mx1, __shfl_xor_sync(0xffffffffu, mx1, 2));
        float s0 = 0.f, s1 = 0.f;
#pragma unroll
        for (int nf = 0; nf < 26; nf++) {
            c[nf][0] = __expf(c[nf][0] - mx0); s0 += c[nf][0];
            c[nf][1] = __expf(c[nf][1] - mx0); s0 += c[nf][1];
            c[nf][2] = __expf(c[nf][2] - mx1); s1 += c[nf][2];
            c[nf][3] = __expf(c[nf][3] - mx1); s1 += c[nf][3];
        }
        s0 += __shfl_xor_sync(0xffffffffu, s0, 1);
        s0 += __shfl_xor_sync(0xffffffffu, s0, 2);
        s1 += __shfl_xor_sync(0xffffffffu, s1, 1);
        s1 += __shfl_xor_sync(0xffffffffu, s1, 2);
        float inv0 = 1.0f / s0, inv1 = 1.0f / s1;

        // O = P * V^T
        float o[8][4];
#pragma unroll
        for (int ne = 0; ne < 8; ne++)
            o[ne][0] = o[ne][1] = o[ne][2] = o[ne][3] = 0.f;

#pragma unroll
        for (int kt = 0; kt < 13; kt++) {
            uint32_t pa[4];
            pa[0] = pack_bf16_f(c[2 * kt][0] * inv0, c[2 * kt][1] * inv0);
            pa[1] = pack_bf16_f(c[2 * kt][2] * inv1, c[2 * kt][3] * inv1);
            pa[2] = pack_bf16_f(c[2 * kt + 1][0] * inv0, c[2 * kt + 1][1] * inv0);
            pa[3] = pack_bf16_f(c[2 * kt + 1][2] * inv1, c[2 * kt + 1][3] * inv1);
#pragma unroll
            for (int ne2 = 0; ne2 < 4; ne2++) {
                int r = ne2 * 16 + (seg >> 1) * 8 + (lane & 7);
                int co = kt * 16 + (seg & 1) * 8;
                uint32_t t4[4];
                LDSM4(t4, smem_u32(&asm_[AOFF_VT + r * VTS + co]));
                mma_bf16(o[2 * ne2 + 0], pa, t4 + 0);
                mma_bf16(o[2 * ne2 + 1], pa, t4 + 2);
            }
        }

        // epilogue: residual add, guarded stores
        int r0 = mt * 16 + (lane >> 2);
        int cb = (lane & 3) * 2;
        if (r0 < SEQL) {
            size_t base = ((size_t)b * SEQL + r0) * HD + h * DH;
#pragma unroll
            for (int ne = 0; ne < 8; ne++) {
                int n = ne * 8 + cb;
                float2 t = *(const float2*)(g_tokens + base + n);
                float2 ov = {t.x + o[ne][0], t.y + o[ne][1]};
                *(float2*)(out + base + n) = ov;
            }
        }
        if (r0 + 8 < SEQL) {
            size_t base = ((size_t)b * SEQL + r0 + 8) * HD + h * DH;
#pragma unroll
            for (int ne = 0; ne < 8; ne++) {
                int n = ne * 8 + cb;
                float2 t = *(const float2*)(g_tokens + base + n);
                float2 ov = {t.x + o[ne][2], t.y + o[ne][3]};
                *(float2*)(out + base + n) = ov;
            }
        }
    }
}

// ---------------- launcher ----------------
extern "C" void kernel_launch(void* const* d_in, const int* in_sizes, int n_in,
                              void* d_out, int out_size) {
    const float* images = (const float*)d_in[0];
    const float* W_map  = (const float*)d_in[1];
    const float* b_map  = (const float*)d_in[2];
    const float* cls    = (const float*)d_in[3];
    const float* ln_w   = (const float*)d_in[4];
    const float* ln_b   = (const float*)d_in[5];
    const float* Wq     = (const float*)d_in[6];
    const float* bq     = (const float*)d_in[7];
    const float* Wk     = (const float*)d_in[8];
    const float* bk     = (const float*)d_in[9];
    const float* Wv     = (const float*)d_in[10];
    const float* bv     = (const float*)d_in[11];
    float* out = (float*)d_out;

    cudaFuncSetAttribute(gemm_tokens_mma, cudaFuncAttributeMaxDynamicSharedMemorySize, G_SMEM);
    cudaFuncSetAttribute(qkv_mma,  cudaFuncAttributeMaxDynamicSharedMemorySize, QKV2_SMEM);
    cudaFuncSetAttribute(attn_mma, cudaFuncAttributeMaxDynamicSharedMemorySize, ATT2_SMEM);

    pos_kernel<<<(SEQL * HD + 255) / 256, 256>>>();
    cls_kernel<<<NB, 256>>>(cls);
    gemm_tokens_mma<<<dim3(HD / 128, (NB * NPAT) / 128), 256, G_SMEM>>>(images, W_map, b_map);
    stats_kernel<<<NB, 1024>>>();
    qkv_mma<<<NB * NH, 256, QKV2_SMEM>>>(ln_w, ln_b, Wq, bq, Wk, bk, Wv, bv);
    attn_mma<<<NB * NH, 256, ATT2_SMEM>>>(out);
}

// round 9
// speedup vs baseline: 3.5030x; 1.0738x over previous
#include <cuda_runtime.h>
#include <cuda_bf16.h>
#include <math.h>
#include <stdint.h>

#define NB   128
#define SEQL 197
#define NPAT 196
#define HD   768
#define NH   12
#define DH   64
#define LN_EPS 1e-5f

// ---------------- scratch (static device globals; no allocs) ----------------
static __device__ float g_tokens[NB * SEQL * HD];          // 77.4 MB
static __device__ float g_pos[SEQL * HD];
static __device__ float g_mean[NB];
static __device__ float g_rstd[NB];

// ================= helpers =================
__device__ __forceinline__ uint32_t smem_u32(const void* p) {
    uint32_t a;
    asm("{ .reg .u64 t; cvta.to.shared.u64 t, %1; cvt.u32.u64 %0, t; }" : "=r"(a) : "l"(p));
    return a;
}
#define LDSM4(r, addr) \
    asm volatile("ldmatrix.sync.aligned.m8n8.x4.shared.b16 {%0,%1,%2,%3}, [%4];" \
        : "=r"((r)[0]), "=r"((r)[1]), "=r"((r)[2]), "=r"((r)[3]) : "r"(addr))

__device__ __forceinline__ void mma_bf16(float* c, const uint32_t* a, const uint32_t* b) {
    asm volatile("mma.sync.aligned.m16n8k16.row.col.f32.bf16.bf16.f32 "
        "{%0,%1,%2,%3}, {%4,%5,%6,%7}, {%8,%9}, {%0,%1,%2,%3};"
        : "+f"(c[0]), "+f"(c[1]), "+f"(c[2]), "+f"(c[3])
        : "r"(a[0]), "r"(a[1]), "r"(a[2]), "r"(a[3]), "r"(b[0]), "r"(b[1]));
}

__device__ __forceinline__ uint32_t pack_bf16(__nv_bfloat16 x, __nv_bfloat16 y) {
    __nv_bfloat162 t = {x, y};
    return *(uint32_t*)&t;
}
__device__ __forceinline__ uint32_t pack_bf16_f(float x, float y) {
    return pack_bf16(__float2bfloat16(x), __float2bfloat16(y));
}
__device__ __forceinline__ void split_f4(float4 v, uint2* hp, uint2* lp) {
    __nv_bfloat16 hx = __float2bfloat16(v.x), hy = __float2bfloat16(v.y);
    __nv_bfloat16 hz = __float2bfloat16(v.z), hw = __float2bfloat16(v.w);
    hp->x = pack_bf16(hx, hy); hp->y = pack_bf16(hz, hw);
    lp->x = pack_bf16_f(v.x - __bfloat162float(hx), v.y - __bfloat162float(hy));
    lp->y = pack_bf16_f(v.z - __bfloat162float(hz), v.w - __bfloat162float(hw));
}

// ---------------- positional embeddings ----------------
__global__ void pos_kernel() {
    int idx = blockIdx.x * blockDim.x + threadIdx.x;
    if (idx >= SEQL * HD) return;
    int i = idx / HD, j = idx % HD;
    float jf = (float)(j & ~1);
    float denom = powf(10000.0f, jf / (float)HD);
    float arg = (float)i / denom;
    g_pos[idx] = (j & 1) ? cosf(arg) : sinf(arg);
}

// ---------------- class token row ----------------
__global__ void cls_kernel(const float* __restrict__ cls) {
    int b = blockIdx.x;
    for (int j = threadIdx.x; j < HD; j += blockDim.x)
        g_tokens[(size_t)b * SEQL * HD + j] = cls[j] + g_pos[j];
}

// ---------------- token projection GEMM: bf16x3 mma, 2-stage pipeline ----------------
// C[m,n] = sum_k A[m,k]*W[n,k]; M=25088, N=768, K=768.
// CTA tile 128x128, BK=64, 8 warps (4m x 2n), warp tile 32x64.
#define KS 72
#define GBUF (512 * KS)   // bf16 elems per stage (AH, AL, BH, BL each 128*KS)
#define G_SMEM (2 * GBUF * 2)

__global__ __launch_bounds__(256) void gemm_tokens_mma(const float* __restrict__ A,
                                                       const float* __restrict__ Wm,
                                                       const float* __restrict__ bias) {
    extern __shared__ char smc[];
    __nv_bfloat16* sm = (__nv_bfloat16*)smc;
    const int tid  = threadIdx.x;
    const int lane = tid & 31, wid = tid >> 5;
    const int wm = wid & 3, wn = wid >> 2;
    const int seg = lane >> 3;
    const int n0 = blockIdx.x * 128;
    const int m0 = blockIdx.y * 128;

    const int srow = tid >> 4, sc4 = (tid & 15) * 4;
    const float* Abase = A + (size_t)(m0 + srow) * HD + sc4;
    const float* Wbase = Wm + (size_t)(n0 + srow) * HD + sc4;

    float4 ra[8], rw[8];
#pragma unroll
    for (int it = 0; it < 8; it++) {
        ra[it] = *(const float4*)(Abase + it * 16 * HD);
        rw[it] = *(const float4*)(Wbase + it * 16 * HD);
    }

    float c[2][8][4] = {};

    for (int kt = 0; kt < 12; kt++) {
        // convert + store current regs into stage kt&1
        __nv_bfloat16* st = sm + (kt & 1) * GBUF;
#pragma unroll
        for (int it = 0; it < 8; it++) {
            int row = srow + it * 16;
            uint2 hp, lp;
            split_f4(ra[it], &hp, &lp);
            *(uint2*)&st[row * KS + sc4] = hp;
            *(uint2*)&st[128 * KS + row * KS + sc4] = lp;
            split_f4(rw[it], &hp, &lp);
            *(uint2*)&st[256 * KS + row * KS + sc4] = hp;
            *(uint2*)&st[384 * KS + row * KS + sc4] = lp;
        }
        __syncthreads();
        // prefetch next tile (LDGs overlap the MMA block below)
        if (kt < 11) {
            int kb = (kt + 1) * 64;
#pragma unroll
            for (int it = 0; it < 8; it++) {
                ra[it] = *(const float4*)(Abase + it * 16 * HD + kb);
                rw[it] = *(const float4*)(Wbase + it * 16 * HD + kb);
            }
        }
        // compute from stage kt&1
#pragma unroll
        for (int ks = 0; ks < 4; ks++) {
            const int k0 = ks * 16;
            uint32_t ah[2][4], al[2][4];
#pragma unroll
            for (int mf = 0; mf < 2; mf++) {
                int r = wm * 32 + mf * 16 + (lane & 15);
                int ko = k0 + (lane >> 4) * 8;
                LDSM4(ah[mf], smem_u32(&st[r * KS + ko]));
                LDSM4(al[mf], smem_u32(&st[128 * KS + r * KS + ko]));
            }
#pragma unroll
            for (int nf2 = 0; nf2 < 4; nf2++) {
                int r = wn * 64 + nf2 * 16 + (seg >> 1) * 8 + (lane & 7);
                int ko = k0 + (seg & 1) * 8;
                uint32_t bh[4], bl[4];
                LDSM4(bh, smem_u32(&st[256 * KS + r * KS + ko]));
                LDSM4(bl, smem_u32(&st[384 * KS + r * KS + ko]));
#pragma unroll
                for (int mf = 0; mf < 2; mf++) {
                    mma_bf16(c[mf][nf2 * 2 + 0], ah[mf], bh + 0);
                    mma_bf16(c[mf][nf2 * 2 + 0], ah[mf], bl + 0);
                    mma_bf16(c[mf][nf2 * 2 + 0], al[mf], bh + 0);
                    mma_bf16(c[mf][nf2 * 2 + 1], ah[mf], bh + 2);
                    mma_bf16(c[mf][nf2 * 2 + 1], ah[mf], bl + 2);
                    mma_bf16(c[mf][nf2 * 2 + 1], al[mf], bh + 2);
                }
            }
        }
    }

#pragma unroll
    for (int mf = 0; mf < 2; mf++) {
#pragma unroll
        for (int half = 0; half < 2; half++) {
            int mg = m0 + wm * 32 + mf * 16 + (lane >> 2) + half * 8;
            int b = mg / NPAT, p = mg % NPAT;
            float* orow = g_tokens + ((size_t)b * SEQL + p + 1) * HD;
            const float* prow = g_pos + (size_t)(p + 1) * HD;
#pragma unroll
            for (int nf = 0; nf < 8; nf++) {
                int col = n0 + wn * 64 + nf * 8 + (lane & 3) * 2;
                float2 o;
                o.x = c[mf][nf][half * 2 + 0] + bias[col] + prow[col];
                o.y = c[mf][nf][half * 2 + 1] + bias[col + 1] + prow[col + 1];
                *(float2*)(orow + col) = o;
            }
        }
    }
}

// ---------------- per-sample LN stats ----------------
__global__ __launch_bounds__(1024) void stats_kernel() {
    int b = blockIdx.x;
    const float4* base = (const float4*)(g_tokens + (size_t)b * SEQL * HD);
    const int n4 = SEQL * HD / 4;
    float s = 0.f, sq = 0.f;
    for (int i = threadIdx.x; i < n4; i += 1024) {
        float4 v = base[i];
        s  += v.x + v.y + v.z + v.w;
        sq += v.x * v.x + v.y * v.y + v.z * v.z + v.w * v.w;
    }
    __shared__ float sh[64];
#pragma unroll
    for (int o = 16; o; o >>= 1) {
        s  += __shfl_xor_sync(0xffffffffu, s, o);
        sq += __shfl_xor_sync(0xffffffffu, sq, o);
    }
    int w = threadIdx.x >> 5, l = threadIdx.x & 31;
    if (!l) { sh[w] = s; sh[32 + w] = sq; }
    __syncthreads();
    if (threadIdx.x == 0) {
        float S = 0.f, Q = 0.f;
        for (int i = 0; i < 32; i++) { S += sh[i]; Q += sh[32 + i]; }
        const float n = (float)(SEQL * HD);
        float mean = S / n;
        float var  = Q / n - mean * mean;
        g_mean[b] = mean;
        g_rstd[b] = rsqrtf(var + LN_EPS);
    }
}

// ---------------- fused QKV + attention (one CTA per (b,h)) ----------------
// Phase 1: X_norm [197x64] staged once (hi/lo), q/k/v mma -> smem K/Q/Vt (bf16).
// Phase 2: flash-style attention from smem, residual-add epilogue.
#define SEQP 208
#define QKS  72
#define VTS  216
#define FXH 0
#define FXL (SEQP * QKS)
#define FWH (2 * SEQP * QKS)
#define FWL (2 * SEQP * QKS + 192 * QKS)
#define FK  (2 * SEQP * QKS + 384 * QKS)
#define FQ  (FK + SEQP * QKS)
#define FVT (FQ + SEQP * QKS)
#define FUSED_SMEM ((FVT + 64 * VTS) * 2)

__global__ void __launch_bounds__(256, 1) qkv_attn_fused(
    const float* __restrict__ lnw, const float* __restrict__ lnb,
    const float* __restrict__ Wq, const float* __restrict__ bq,
    const float* __restrict__ Wk, const float* __restrict__ bk,
    const float* __restrict__ Wv, const float* __restrict__ bv,
    float* __restrict__ out) {
    extern __shared__ __nv_bfloat16 fsm[];
    const int tid = threadIdx.x, lane = tid & 31, w = tid >> 5;
    const int seg = lane >> 3;
    const int bh = blockIdx.x, b = bh / NH, h = bh % NH;
    const float mean = g_mean[b], rstd = g_rstd[b];
    const float* tb = g_tokens + (size_t)b * SEQL * HD + h * DH;

    // ---- phase 0: stage X normalized (hi/lo) and W (hi/lo) ----
    for (int idx = tid; idx < SEQP * 16; idx += 256) {
        int s = idx >> 4, d4 = (idx & 15) * 4;
        float4 x = {0.f, 0.f, 0.f, 0.f};
        if (s < SEQL) {
            float4 tv = *(const float4*)(tb + (size_t)s * HD + d4);
            float4 wv = *(const float4*)(lnw + (size_t)s * HD + h * DH + d4);
            float4 bb = *(const float4*)(lnb + (size_t)s * HD + h * DH + d4);
            x.x = (tv.x - mean) * rstd * wv.x + bb.x;
            x.y = (tv.y - mean) * rstd * wv.y + bb.y;
            x.z = (tv.z - mean) * rstd * wv.z + bb.z;
            x.w = (tv.w - mean) * rstd * wv.w + bb.w;
        }
        uint2 hp, lp;
        split_f4(x, &hp, &lp);
        *(uint2*)&fsm[FXH + s * QKS + d4] = hp;
        *(uint2*)&fsm[FXL + s * QKS + d4] = lp;
    }
    for (int idx = tid; idx < 3 * 64 * 16; idx += 256) {
        int m = idx >> 10, rem = idx & 1023;
        int e = rem >> 4, d4 = (rem & 15) * 4;
        const float* Wsrc = (m == 0 ? Wq : (m == 1 ? Wk : Wv)) + (size_t)h * DH * DH;
        float4 v = *(const float4*)(Wsrc + e * DH + d4);
        uint2 hp, lp;
        split_f4(v, &hp, &lp);
        *(uint2*)&fsm[FWH + (m * 64 + e) * QKS + d4] = hp;
        *(uint2*)&fsm[FWL + (m * 64 + e) * QKS + d4] = lp;
    }
    __syncthreads();

    // ---- phase 1: 39 tasks (mt 0..12 x m 0..2) -> K/Q/Vt smem ----
    for (int t = w; t < 39; t += 8) {
        const int mt = t / 3, m = t % 3;
        float c[8][4] = {};
#pragma unroll
        for (int ks = 0; ks < 4; ks++) {
            const int k0 = ks * 16;
            uint32_t ah[4], al[4];
            {
                int r = mt * 16 + (lane & 15);
                int ko = k0 + (lane >> 4) * 8;
                LDSM4(ah, smem_u32(&fsm[FXH + r * QKS + ko]));
                LDSM4(al, smem_u32(&fsm[FXL + r * QKS + ko]));
            }
#pragma unroll
            for (int nf2 = 0; nf2 < 4; nf2++) {
                int r = m * 64 + nf2 * 16 + (seg >> 1) * 8 + (lane & 7);
                int ko = k0 + (seg & 1) * 8;
                uint32_t bh2[4], bl2[4];
                LDSM4(bh2, smem_u32(&fsm[FWH + r * QKS + ko]));
                LDSM4(bl2, smem_u32(&fsm[FWL + r * QKS + ko]));
                mma_bf16(c[nf2 * 2 + 0], ah, bh2 + 0);
                mma_bf16(c[nf2 * 2 + 0], ah, bl2 + 0);
                mma_bf16(c[nf2 * 2 + 0], al, bh2 + 0);
                mma_bf16(c[nf2 * 2 + 1], ah, bh2 + 2);
                mma_bf16(c[nf2 * 2 + 1], ah, bl2 + 2);
                mma_bf16(c[nf2 * 2 + 1], al, bh2 + 2);
            }
        }
        const float* bias = (m == 0 ? bq : (m == 1 ? bk : bv)) + h * DH;
        int r0 = mt * 16 + (lane >> 2);
#pragma unroll
        for (int half = 0; half < 2; half++) {
            int r = r0 + half * 8;   // always < 208; padded rows hold bias (inert)
#pragma unroll
            for (int nf = 0; nf < 8; nf++) {
                int e = nf * 8 + (lane & 3) * 2;
                float v0 = c[nf][half * 2 + 0] + bias[e];
                float v1 = c[nf][half * 2 + 1] + bias[e + 1];
                if (m == 0) {
                    *(uint32_t*)&fsm[FQ + r * QKS + e] = pack_bf16_f(v0 * 0.125f, v1 * 0.125f);
                } else if (m == 1) {
                    *(uint32_t*)&fsm[FK + r * QKS + e] = pack_bf16_f(v0, v1);
                } else {
                    fsm[FVT + e * VTS + r] = __float2bfloat16(v0);
                    fsm[FVT + (e + 1) * VTS + r] = __float2bfloat16(v1);
                }
            }
        }
    }
    __syncthreads();

    // ---- phase 2: attention ----
    for (int mt = w; mt < 13; mt += 8) {
        float c[26][4];
#pragma unroll
        for (int nf = 0; nf < 26; nf++)
            c[nf][0] = c[nf][1] = c[nf][2] = c[nf][3] = 0.f;

        // S = Qs * K^T
#pragma unroll
        for (int ksx = 0; ksx < 4; ksx++) {
            uint32_t a[4];
            {
                int r = mt * 16 + (lane & 15);
                int co = ksx * 16 + (lane >> 4) * 8;
                LDSM4(a, smem_u32(&fsm[FQ + r * QKS + co]));
            }
#pragma unroll
            for (int nf2 = 0; nf2 < 13; nf2++) {
                int r = nf2 * 16 + (seg >> 1) * 8 + (lane & 7);
                int co = ksx * 16 + (seg & 1) * 8;
                uint32_t t4[4];
                LDSM4(t4, smem_u32(&fsm[FK + r * QKS + co]));
                mma_bf16(c[2 * nf2 + 0], a, t4 + 0);
                mma_bf16(c[2 * nf2 + 1], a, t4 + 2);
            }
        }

        // mask padded columns (cols >= 197)
        {
            int cb = (lane & 3) * 2;
            if (192 + cb >= SEQL) { c[24][0] = -1e30f; c[24][2] = -1e30f; }
            if (193 + cb >= SEQL) { c[24][1] = -1e30f; c[24][3] = -1e30f; }
            c[25][0] = c[25][1] = c[25][2] = c[25][3] = -1e30f;
        }

        // softmax in registers
        float mx0 = -1e30f, mx1 = -1e30f;
#pragma unroll
        for (int nf = 0; nf < 26; nf++) {
            mx0 = fmaxf(mx0, fmaxf(c[nf][0], c[nf][1]));
            mx1 = fmaxf(mx1, fmaxf(c[nf][2], c[nf][3]));
        }
        mx0 = fmaxf(mx0, __shfl_xor_sync(0xffffffffu, mx0, 1));
        mx0 = fmaxf(mx0, __shfl_xor_sync(0xffffffffu, mx0, 2));
        mx1 = fmaxf(mx1, __shfl_xor_sync(0xffffffffu, mx1, 1));
        mx1 = fmaxf(mx1, __shfl_xor_sync(0xffffffffu, mx1, 2));
        float s0 = 0.f, s1 = 0.f;
#pragma unroll
        for (int nf = 0; nf < 26; nf++) {
            c[nf][0] = __expf(c[nf][0] - mx0); s0 += c[nf][0];
            c[nf][1] = __expf(c[nf][1] - mx0); s0 += c[nf][1];
            c[nf][2] = __expf(c[nf][2] - mx1); s1 += c[nf][2];
            c[nf][3] = __expf(c[nf][3] - mx1); s1 += c[nf][3];
        }
        s0 += __shfl_xor_sync(0xffffffffu, s0, 1);
        s0 += __shfl_xor_sync(0xffffffffu, s0, 2);
        s1 += __shfl_xor_sync(0xffffffffu, s1, 1);
        s1 += __shfl_xor_sync(0xffffffffu, s1, 2);
        float inv0 = 1.0f / s0, inv1 = 1.0f / s1;

        // O = P * V^T
        float o[8][4];
#pragma unroll
        for (int ne = 0; ne < 8; ne++)
            o[ne][0] = o[ne][1] = o[ne][2] = o[ne][3] = 0.f;

#pragma unroll
        for (int kt = 0; kt < 13; kt++) {
            uint32_t pa[4];
            pa[0] = pack_bf16_f(c[2 * kt][0] * inv0, c[2 * kt][1] * inv0);
            pa[1] = pack_bf16_f(c[2 * kt][2] * inv1, c[2 * kt][3] * inv1);
            pa[2] = pack_bf16_f(c[2 * kt + 1][0] * inv0, c[2 * kt + 1][1] * inv0);
            pa[3] = pack_bf16_f(c[2 * kt + 1][2] * inv1, c[2 * kt + 1][3] * inv1);
#pragma unroll
            for (int ne2 = 0; ne2 < 4; ne2++) {
                int r = ne2 * 16 + (seg >> 1) * 8 + (lane & 7);
                int co = kt * 16 + (seg & 1) * 8;
                uint32_t t4[4];
                LDSM4(t4, smem_u32(&fsm[FVT + r * VTS + co]));
                mma_bf16(o[2 * ne2 + 0], pa, t4 + 0);
                mma_bf16(o[2 * ne2 + 1], pa, t4 + 2);
            }
        }

        // epilogue: residual add, guarded stores
        int r0 = mt * 16 + (lane >> 2);
        int cb = (lane & 3) * 2;
        if (r0 < SEQL) {
            size_t base = ((size_t)b * SEQL + r0) * HD + h * DH;
#pragma unroll
            for (int ne = 0; ne < 8; ne++) {
                int n = ne * 8 + cb;
                float2 t = *(const float2*)(g_tokens + base + n);
                float2 ov = {t.x + o[ne][0], t.y + o[ne][1]};
                *(float2*)(out + base + n) = ov;
            }
        }
        if (r0 + 8 < SEQL) {
            size_t base = ((size_t)b * SEQL + r0 + 8) * HD + h * DH;
#pragma unroll
            for (int ne = 0; ne < 8; ne++) {
                int n = ne * 8 + cb;
                float2 t = *(const float2*)(g_tokens + base + n);
                float2 ov = {t.x + o[ne][2], t.y + o[ne][3]};
                *(float2*)(out + base + n) = ov;
            }
        }
    }
}

// ---------------- launcher ----------------
extern "C" void kernel_launch(void* const* d_in, const int* in_sizes, int n_in,
                              void* d_out, int out_size) {
    const float* images = (const float*)d_in[0];
    const float* W_map  = (const float*)d_in[1];
    const float* b_map  = (const float*)d_in[2];
    const float* cls    = (const float*)d_in[3];
    const float* ln_w   = (const float*)d_in[4];
    const float* ln_b   = (const float*)d_in[5];
    const float* Wq     = (const float*)d_in[6];
    const float* bq     = (const float*)d_in[7];
    const float* Wk     = (const float*)d_in[8];
    const float* bk     = (const float*)d_in[9];
    const float* Wv     = (const float*)d_in[10];
    const float* bv     = (const float*)d_in[11];
    float* out = (float*)d_out;

    cudaFuncSetAttribute(gemm_tokens_mma, cudaFuncAttributeMaxDynamicSharedMemorySize, G_SMEM);
    cudaFuncSetAttribute(qkv_attn_fused, cudaFuncAttributeMaxDynamicSharedMemorySize, FUSED_SMEM);

    pos_kernel<<<(SEQL * HD + 255) / 256, 256>>>();
    cls_kernel<<<NB, 256>>>(cls);
    gemm_tokens_mma<<<dim3(HD / 128, (NB * NPAT) / 128), 256, G_SMEM>>>(images, W_map, b_map);
    stats_kernel<<<NB, 1024>>>();
    qkv_attn_fused<<<NB * NH, 256, FUSED_SMEM>>>(ln_w, ln_b, Wq, bq, Wk, bk, Wv, bv, out);
}

// round 10
// speedup vs baseline: 5.0496x; 1.4415x over previous
#include <cuda_runtime.h>
#include <cuda_fp16.h>
#include <math.h>
#include <stdint.h>

#define NB   128
#define SEQL 197
#define NPAT 196
#define HD   768
#define NH   12
#define DH   64
#define LN_EPS 1e-5f

// ---------------- scratch (static device globals; no allocs) ----------------
static __device__ float g_tokens[NB * SEQL * HD];          // 77.4 MB
static __device__ float g_pos[SEQL * HD];
static __device__ float g_mean[NB];
static __device__ float g_rstd[NB];

// ================= helpers =================
__device__ __forceinline__ uint32_t smem_u32(const void* p) {
    uint32_t a;
    asm("{ .reg .u64 t; cvta.to.shared.u64 t, %1; cvt.u32.u64 %0, t; }" : "=r"(a) : "l"(p));
    return a;
}
#define LDSM4(r, addr) \
    asm volatile("ldmatrix.sync.aligned.m8n8.x4.shared.b16 {%0,%1,%2,%3}, [%4];" \
        : "=r"((r)[0]), "=r"((r)[1]), "=r"((r)[2]), "=r"((r)[3]) : "r"(addr))

__device__ __forceinline__ void mma_f16(float* c, const uint32_t* a, const uint32_t* b) {
    asm volatile("mma.sync.aligned.m16n8k16.row.col.f32.f16.f16.f32 "
        "{%0,%1,%2,%3}, {%4,%5,%6,%7}, {%8,%9}, {%0,%1,%2,%3};"
        : "+f"(c[0]), "+f"(c[1]), "+f"(c[2]), "+f"(c[3])
        : "r"(a[0]), "r"(a[1]), "r"(a[2]), "r"(a[3]), "r"(b[0]), "r"(b[1]));
}

__device__ __forceinline__ uint32_t pack_h_f(float x, float y) {
    __half2 t = __floats2half2_rn(x, y);
    return *(uint32_t*)&t;
}
__device__ __forceinline__ uint2 cvt_f4(float4 v) {
    uint2 r;
    r.x = pack_h_f(v.x, v.y);
    r.y = pack_h_f(v.z, v.w);
    return r;
}

// ---------------- positional embeddings ----------------
__global__ void pos_kernel() {
    int idx = blockIdx.x * blockDim.x + threadIdx.x;
    if (idx >= SEQL * HD) return;
    int i = idx / HD, j = idx % HD;
    float jf = (float)(j & ~1);
    float denom = powf(10000.0f, jf / (float)HD);
    float arg = (float)i / denom;
    g_pos[idx] = (j & 1) ? cosf(arg) : sinf(arg);
}

// ---------------- class token row ----------------
__global__ void cls_kernel(const float* __restrict__ cls) {
    int b = blockIdx.x;
    for (int j = threadIdx.x; j < HD; j += blockDim.x)
        g_tokens[(size_t)b * SEQL * HD + j] = cls[j] + g_pos[j];
}

// ---------------- token projection GEMM: fp16 mma, double-buffered, 2 CTA/SM ----
// C[m,n] = sum_k A[m,k]*W[n,k]; M=25088, N=768, K=768.
// CTA tile 128x128, BK=64, 8 warps (4m x 2n), warp tile 32x64.
#define KS 72
#define GBUF (256 * KS)           // A[128][72] + B[128][72] fp16 elems per stage
#define G_SMEM (2 * GBUF * 2)     // 73728 bytes

__global__ __launch_bounds__(256, 2) void gemm_tokens_mma(const float* __restrict__ A,
                                                          const float* __restrict__ Wm,
                                                          const float* __restrict__ bias) {
    extern __shared__ char smc[];
    __half* sm = (__half*)smc;
    const int tid  = threadIdx.x;
    const int lane = tid & 31, wid = tid >> 5;
    const int wm = wid & 3, wn = wid >> 2;
    const int seg = lane >> 3;
    const int n0 = blockIdx.x * 128;
    const int m0 = blockIdx.y * 128;

    const int srow = tid >> 4, sc4 = (tid & 15) * 4;
    const float* Abase = A + (size_t)(m0 + srow) * HD + sc4;
    const float* Wbase = Wm + (size_t)(n0 + srow) * HD + sc4;

    float c[2][8][4] = {};

    for (int kt = 0; kt < 12; kt++) {
        __half* st = sm + (kt & 1) * GBUF;
        const int kb = kt * 64;
#pragma unroll
        for (int it = 0; it < 8; it++) {
            int row = srow + it * 16;
            float4 va = *(const float4*)(Abase + it * 16 * HD + kb);
            float4 vw = *(const float4*)(Wbase + it * 16 * HD + kb);
            *(uint2*)&st[row * KS + sc4] = cvt_f4(va);
            *(uint2*)&st[128 * KS + row * KS + sc4] = cvt_f4(vw);
        }
        __syncthreads();
#pragma unroll
        for (int ks = 0; ks < 4; ks++) {
            const int k0 = ks * 16;
            uint32_t a[2][4];
#pragma unroll
            for (int mf = 0; mf < 2; mf++) {
                int r = wm * 32 + mf * 16 + (lane & 15);
                int ko = k0 + (lane >> 4) * 8;
                LDSM4(a[mf], smem_u32(&st[r * KS + ko]));
            }
#pragma unroll
            for (int nf2 = 0; nf2 < 4; nf2++) {
                int r = wn * 64 + nf2 * 16 + (seg >> 1) * 8 + (lane & 7);
                int ko = k0 + (seg & 1) * 8;
                uint32_t bfr[4];
                LDSM4(bfr, smem_u32(&st[128 * KS + r * KS + ko]));
#pragma unroll
                for (int mf = 0; mf < 2; mf++) {
                    mma_f16(c[mf][nf2 * 2 + 0], a[mf], bfr + 0);
                    mma_f16(c[mf][nf2 * 2 + 1], a[mf], bfr + 2);
                }
            }
        }
    }

#pragma unroll
    for (int mf = 0; mf < 2; mf++) {
#pragma unroll
        for (int half = 0; half < 2; half++) {
            int mg = m0 + wm * 32 + mf * 16 + (lane >> 2) + half * 8;
            int b = mg / NPAT, p = mg % NPAT;
            float* orow = g_tokens + ((size_t)b * SEQL + p + 1) * HD;
            const float* prow = g_pos + (size_t)(p + 1) * HD;
#pragma unroll
            for (int nf = 0; nf < 8; nf++) {
                int col = n0 + wn * 64 + nf * 8 + (lane & 3) * 2;
                float2 o;
                o.x = c[mf][nf][half * 2 + 0] + bias[col] + prow[col];
                o.y = c[mf][nf][half * 2 + 1] + bias[col + 1] + prow[col + 1];
                *(float2*)(orow + col) = o;
            }
        }
    }
}

// ---------------- per-sample LN stats ----------------
__global__ __launch_bounds__(1024) void stats_kernel() {
    int b = blockIdx.x;
    const float4* base = (const float4*)(g_tokens + (size_t)b * SEQL * HD);
    const int n4 = SEQL * HD / 4;
    float s = 0.f, sq = 0.f;
    for (int i = threadIdx.x; i < n4; i += 1024) {
        float4 v = base[i];
        s  += v.x + v.y + v.z + v.w;
        sq += v.x * v.x + v.y * v.y + v.z * v.z + v.w * v.w;
    }
    __shared__ float sh[64];
#pragma unroll
    for (int o = 16; o; o >>= 1) {
        s  += __shfl_xor_sync(0xffffffffu, s, o);
        sq += __shfl_xor_sync(0xffffffffu, sq, o);
    }
    int w = threadIdx.x >> 5, l = threadIdx.x & 31;
    if (!l) { sh[w] = s; sh[32 + w] = sq; }
    __syncthreads();
    if (threadIdx.x == 0) {
        float S = 0.f, Q = 0.f;
        for (int i = 0; i < 32; i++) { S += sh[i]; Q += sh[32 + i]; }
        const float n = (float)(SEQL * HD);
        float mean = S / n;
        float var  = Q / n - mean * mean;
        g_mean[b] = mean;
        g_rstd[b] = rsqrtf(var + LN_EPS);
    }
}

// ---------------- fused QKV + attention (one CTA per (b,h)), fp16 ----------------
#define SEQP 208
#define QKS  72
#define VTS  216
#define FX  0
#define FW  (SEQP * QKS)
#define FK  (SEQP * QKS + 192 * QKS)
#define FQ  (FK + SEQP * QKS)
#define FVT (FQ + SEQP * QKS)
#define FUSED_SMEM ((FVT + 64 * VTS) * 2)

__global__ void __launch_bounds__(256, 1) qkv_attn_fused(
    const float* __restrict__ lnw, const float* __restrict__ lnb,
    const float* __restrict__ Wq, const float* __restrict__ bq,
    const float* __restrict__ Wk, const float* __restrict__ bk,
    const float* __restrict__ Wv, const float* __restrict__ bv,
    float* __restrict__ out) {
    extern __shared__ __half fsm[];
    const int tid = threadIdx.x, lane = tid & 31, w = tid >> 5;
    const int seg = lane >> 3;
    const int bh = blockIdx.x, b = bh / NH, h = bh % NH;
    const float mean = g_mean[b], rstd = g_rstd[b];
    const float* tb = g_tokens + (size_t)b * SEQL * HD + h * DH;

    // ---- phase 0: stage X normalized (fp16) and W (fp16) ----
    for (int idx = tid; idx < SEQP * 16; idx += 256) {
        int s = idx >> 4, d4 = (idx & 15) * 4;
        float4 x = {0.f, 0.f, 0.f, 0.f};
        if (s < SEQL) {
            float4 tv = *(const float4*)(tb + (size_t)s * HD + d4);
            float4 wv = *(const float4*)(lnw + (size_t)s * HD + h * DH + d4);
            float4 bb = *(const float4*)(lnb + (size_t)s * HD + h * DH + d4);
            x.x = (tv.x - mean) * rstd * wv.x + bb.x;
            x.y = (tv.y - mean) * rstd * wv.y + bb.y;
            x.z = (tv.z - mean) * rstd * wv.z + bb.z;
            x.w = (tv.w - mean) * rstd * wv.w + bb.w;
        }
        *(uint2*)&fsm[FX + s * QKS + d4] = cvt_f4(x);
    }
    for (int idx = tid; idx < 3 * 64 * 16; idx += 256) {
        int m = idx >> 10, rem = idx & 1023;
        int e = rem >> 4, d4 = (rem & 15) * 4;
        const float* Wsrc = (m == 0 ? Wq : (m == 1 ? Wk : Wv)) + (size_t)h * DH * DH;
        float4 v = *(const float4*)(Wsrc + e * DH + d4);
        *(uint2*)&fsm[FW + (m * 64 + e) * QKS + d4] = cvt_f4(v);
    }
    __syncthreads();

    // ---- phase 1: 39 tasks (mt 0..12 x m 0..2) -> K/Q/Vt smem ----
    for (int t = w; t < 39; t += 8) {
        const int mt = t / 3, m = t % 3;
        float c[8][4] = {};
#pragma unroll
        for (int ks = 0; ks < 4; ks++) {
            const int k0 = ks * 16;
            uint32_t a[4];
            {
                int r = mt * 16 + (lane & 15);
                int ko = k0 + (lane >> 4) * 8;
                LDSM4(a, smem_u32(&fsm[FX + r * QKS + ko]));
            }
#pragma unroll
            for (int nf2 = 0; nf2 < 4; nf2++) {
                int r = m * 64 + nf2 * 16 + (seg >> 1) * 8 + (lane & 7);
                int ko = k0 + (seg & 1) * 8;
                uint32_t bfr[4];
                LDSM4(bfr, smem_u32(&fsm[FW + r * QKS + ko]));
                mma_f16(c[nf2 * 2 + 0], a, bfr + 0);
                mma_f16(c[nf2 * 2 + 1], a, bfr + 2);
            }
        }
        const float* bias = (m == 0 ? bq : (m == 1 ? bk : bv)) + h * DH;
        int r0 = mt * 16 + (lane >> 2);
#pragma unroll
        for (int half = 0; half < 2; half++) {
            int r = r0 + half * 8;   // < 208; padded rows hold bias (inert)
#pragma unroll
            for (int nf = 0; nf < 8; nf++) {
                int e = nf * 8 + (lane & 3) * 2;
                float v0 = c[nf][half * 2 + 0] + bias[e];
                float v1 = c[nf][half * 2 + 1] + bias[e + 1];
                if (m == 0) {
                    *(uint32_t*)&fsm[FQ + r * QKS + e] = pack_h_f(v0 * 0.125f, v1 * 0.125f);
                } else if (m == 1) {
                    *(uint32_t*)&fsm[FK + r * QKS + e] = pack_h_f(v0, v1);
                } else {
                    fsm[FVT + e * VTS + r] = __float2half_rn(v0);
                    fsm[FVT + (e + 1) * VTS + r] = __float2half_rn(v1);
                }
            }
        }
    }
    __syncthreads();

    // ---- phase 2: attention ----
    for (int mt = w; mt < 13; mt += 8) {
        float c[26][4];
#pragma unroll
        for (int nf = 0; nf < 26; nf++)
            c[nf][0] = c[nf][1] = c[nf][2] = c[nf][3] = 0.f;

        // S = Qs * K^T
#pragma unroll
        for (int ksx = 0; ksx < 4; ksx++) {
            uint32_t a[4];
            {
                int r = mt * 16 + (lane & 15);
                int co = ksx * 16 + (lane >> 4) * 8;
                LDSM4(a, smem_u32(&fsm[FQ + r * QKS + co]));
            }
#pragma unroll
            for (int nf2 = 0; nf2 < 13; nf2++) {
                int r = nf2 * 16 + (seg >> 1) * 8 + (lane & 7);
                int co = ksx * 16 + (seg & 1) * 8;
                uint32_t t4[4];
                LDSM4(t4, smem_u32(&fsm[FK + r * QKS + co]));
                mma_f16(c[2 * nf2 + 0], a, t4 + 0);
                mma_f16(c[2 * nf2 + 1], a, t4 + 2);
            }
        }

        // mask padded columns (cols >= 197)
        {
            int cb = (lane & 3) * 2;
            if (192 + cb >= SEQL) { c[24][0] = -1e30f; c[24][2] = -1e30f; }
            if (193 + cb >= SEQL) { c[24][1] = -1e30f; c[24][3] = -1e30f; }
            c[25][0] = c[25][1] = c[25][2] = c[25][3] = -1e30f;
        }

        // softmax in registers
        float mx0 = -1e30f, mx1 = -1e30f;
#pragma unroll
        for (int nf = 0; nf < 26; nf++) {
            mx0 = fmaxf(mx0, fmaxf(c[nf][0], c[nf][1]));
            mx1 = fmaxf(mx1, fmaxf(c[nf][2], c[nf][3]));
        }
        mx0 = fmaxf(mx0, __shfl_xor_sync(0xffffffffu, mx0, 1));
        mx0 = fmaxf(mx0, __shfl_xor_sync(0xffffffffu, mx0, 2));
        mx1 = fmaxf(mx1, __shfl_xor_sync(0xffffffffu, mx1, 1));
        mx1 = fmaxf(mx1, __shfl_xor_sync(0xffffffffu, mx1, 2));
        float s0 = 0.f, s1 = 0.f;
#pragma unroll
        for (int nf = 0; nf < 26; nf++) {
            c[nf][0] = __expf(c[nf][0] - mx0); s0 += c[nf][0];
            c[nf][1] = __expf(c[nf][1] - mx0); s0 += c[nf][1];
            c[nf][2] = __expf(c[nf][2] - mx1); s1 += c[nf][2];
            c[nf][3] = __expf(c[nf][3] - mx1); s1 += c[nf][3];
        }
        s0 += __shfl_xor_sync(0xffffffffu, s0, 1);
        s0 += __shfl_xor_sync(0xffffffffu, s0, 2);
        s1 += __shfl_xor_sync(0xffffffffu, s1, 1);
        s1 += __shfl_xor_sync(0xffffffffu, s1, 2);
        float inv0 = 1.0f / s0, inv1 = 1.0f / s1;

        // O = P * V^T
        float o[8][4];
#pragma unroll
        for (int ne = 0; ne < 8; ne++)
            o[ne][0] = o[ne][1] = o[ne][2] = o[ne][3] = 0.f;

#pragma unroll
        for (int kt = 0; kt < 13; kt++) {
            uint32_t pa[4];
            pa[0] = pack_h_f(c[2 * kt][0] * inv0, c[2 * kt][1] * inv0);
            pa[1] = pack_h_f(c[2 * kt][2] * inv1, c[2 * kt][3] * inv1);
            pa[2] = pack_h_f(c[2 * kt + 1][0] * inv0, c[2 * kt + 1][1] * inv0);
            pa[3] = pack_h_f(c[2 * kt + 1][2] * inv1, c[2 * kt + 1][3] * inv1);
#pragma unroll
            for (int ne2 = 0; ne2 < 4; ne2++) {
                int r = ne2 * 16 + (seg >> 1) * 8 + (lane & 7);
                int co = kt * 16 + (seg & 1) * 8;
                uint32_t t4[4];
                LDSM4(t4, smem_u32(&fsm[FVT + r * VTS + co]));
                mma_f16(o[2 * ne2 + 0], pa, t4 + 0);
                mma_f16(o[2 * ne2 + 1], pa, t4 + 2);
            }
        }

        // epilogue: residual add, guarded stores
        int r0 = mt * 16 + (lane >> 2);
        int cb = (lane & 3) * 2;
        if (r0 < SEQL) {
            size_t base = ((size_t)b * SEQL + r0) * HD + h * DH;
#pragma unroll
            for (int ne = 0; ne < 8; ne++) {
                int n = ne * 8 + cb;
                float2 t = *(const float2*)(g_tokens + base + n);
                float2 ov = {t.x + o[ne][0], t.y + o[ne][1]};
                *(float2*)(out + base + n) = ov;
            }
        }
        if (r0 + 8 < SEQL) {
            size_t base = ((size_t)b * SEQL + r0 + 8) * HD + h * DH;
#pragma unroll
            for (int ne = 0; ne < 8; ne++) {
                int n = ne * 8 + cb;
                float2 t = *(const float2*)(g_tokens + base + n);
                float2 ov = {t.x + o[ne][2], t.y + o[ne][3]};
                *(float2*)(out + base + n) = ov;
            }
        }
    }
}

// ---------------- launcher ----------------
extern "C" void kernel_launch(void* const* d_in, const int* in_sizes, int n_in,
                              void* d_out, int out_size) {
    const float* images = (const float*)d_in[0];
    const float* W_map  = (const float*)d_in[1];
    const float* b_map  = (const float*)d_in[2];
    const float* cls    = (const float*)d_in[3];
    const float* ln_w   = (const float*)d_in[4];
    const float* ln_b   = (const float*)d_in[5];
    const float* Wq     = (const float*)d_in[6];
    const float* bq     = (const float*)d_in[7];
    const float* Wk     = (const float*)d_in[8];
    const float* bk     = (const float*)d_in[9];
    const float* Wv     = (const float*)d_in[10];
    const float* bv     = (const float*)d_in[11];
    float* out = (float*)d_out;

    cudaFuncSetAttribute(gemm_tokens_mma, cudaFuncAttributeMaxDynamicSharedMemorySize, G_SMEM);
    cudaFuncSetAttribute(qkv_attn_fused, cudaFuncAttributeMaxDynamicSharedMemorySize, FUSED_SMEM);

    pos_kernel<<<(SEQL * HD + 255) / 256, 256>>>();
    cls_kernel<<<NB, 256>>>(cls);
    gemm_tokens_mma<<<dim3(HD / 128, (NB * NPAT) / 128), 256, G_SMEM>>>(images, W_map, b_map);
    stats_kernel<<<NB, 1024>>>();
    qkv_attn_fused<<<NB * NH, 256, FUSED_SMEM>>>(ln_w, ln_b, Wq, bq, Wk, bk, Wv, bv, out);
}

// round 12
// speedup vs baseline: 6.2322x; 1.2342x over previous
#include <cuda_runtime.h>
#include <cuda_fp16.h>
#include <math.h>
#include <stdint.h>

#define NB   128
#define SEQL 197
#define NPAT 196
#define HD   768
#define NH   12
#define DH   64
#define LN_EPS 1e-5f
#define NA   (NB * NPAT * HD)   // 19267584 image elems
#define NW   (HD * HD)

// ---------------- scratch (static device globals; no allocs) ----------------
static __device__ float g_tokens[NB * SEQL * HD];          // 77.4 MB
static __device__ float g_pos[SEQL * HD];
static __device__ float g_mean[NB];
static __device__ float g_rstd[NB];
static __device__ __half g_Ah[NA];                          // fp16 images
static __device__ __half g_Wh[NW];                          // fp16 W_map

// ================= helpers =================
__device__ __forceinline__ uint32_t smem_u32(const void* p) {
    uint32_t a;
    asm("{ .reg .u64 t; cvta.to.shared.u64 t, %1; cvt.u32.u64 %0, t; }" : "=r"(a) : "l"(p));
    return a;
}
#define LDSM4(r, addr) \
    asm volatile("ldmatrix.sync.aligned.m8n8.x4.shared.b16 {%0,%1,%2,%3}, [%4];" \
        : "=r"((r)[0]), "=r"((r)[1]), "=r"((r)[2]), "=r"((r)[3]) : "r"(addr))

__device__ __forceinline__ void mma_f16(float* c, const uint32_t* a, const uint32_t* b) {
    asm volatile("mma.sync.aligned.m16n8k16.row.col.f32.f16.f16.f32 "
        "{%0,%1,%2,%3}, {%4,%5,%6,%7}, {%8,%9}, {%0,%1,%2,%3};"
        : "+f"(c[0]), "+f"(c[1]), "+f"(c[2]), "+f"(c[3])
        : "r"(a[0]), "r"(a[1]), "r"(a[2]), "r"(a[3]), "r"(b[0]), "r"(b[1]));
}

__device__ __forceinline__ uint32_t pack_h_f(float x, float y) {
    __half2 t = __floats2half2_rn(x, y);
    return *(uint32_t*)&t;
}
__device__ __forceinline__ uint2 cvt_f4(float4 v) {
    uint2 r;
    r.x = pack_h_f(v.x, v.y);
    r.y = pack_h_f(v.z, v.w);
    return r;
}

// ---------------- positional embeddings ----------------
__global__ void pos_kernel() {
    int idx = blockIdx.x * blockDim.x + threadIdx.x;
    if (idx >= SEQL * HD) return;
    int i = idx / HD, j = idx % HD;
    float jf = (float)(j & ~1);
    float denom = powf(10000.0f, jf / (float)HD);
    float arg = (float)i / denom;
    g_pos[idx] = (j & 1) ? cosf(arg) : sinf(arg);
}

// ---------------- class token row ----------------
__global__ void cls_kernel(const float* __restrict__ cls) {
    int b = blockIdx.x;
    for (int j = threadIdx.x; j < HD; j += blockDim.x)
        g_tokens[(size_t)b * SEQL * HD + j] = cls[j] + g_pos[j];
}

// ---------------- fp32 -> fp16 pre-convert (images + W_map) ----------------
__global__ __launch_bounds__(256) void cvt_kernel(const float* __restrict__ A,
                                                  const float* __restrict__ Wm) {
    const int stride = gridDim.x * blockDim.x;
    const int tot4 = (NA + NW) / 4;
    for (int i = blockIdx.x * blockDim.x + threadIdx.x; i < tot4; i += stride) {
        if (i < NA / 4) {
            float4 v = ((const float4*)A)[i];
            *(uint2*)&g_Ah[(size_t)i * 4] = cvt_f4(v);
        } else {
            int j = i - NA / 4;
            float4 v = ((const float4*)Wm)[j];
            *(uint2*)&g_Wh[(size_t)j * 4] = cvt_f4(v);
        }
    }
}

// ---------------- token projection GEMM: fp16 mma + cp.async 3-stage ----------
// C[m,n] = sum_k A[m,k]*W[n,k]; M=25088, N=768, K=768.
// CTA tile 128x128, BK=64, 8 warps (4m x 2n), warp tile 32x64. 2 CTA/SM.
#define KS 72
#define GST (256 * KS)            // halves per stage: A[128][72] + W[128][72]
#define G_SMEM (3 * GST * 2)      // 110592 bytes

#define GEMM_ISSUE(ktile) do { \
    __half* st_ = sm + ((ktile) % 3) * GST; \
    const int kb_ = (ktile) * 64; \
    _Pragma("unroll") \
    for (int it = 0; it < 8; it++) { \
        int ch = it * 256 + tid; \
        int row = ch >> 3, c8 = ch & 7; \
        const __half* src = (row < 128) \
            ? (g_Ah + (size_t)(m0 + row) * HD + kb_ + c8 * 8) \
            : (g_Wh + (size_t)(n0 + row - 128) * HD + kb_ + c8 * 8); \
        uint32_t dst = smem_u32(&st_[row * KS + c8 * 8]); \
        asm volatile("cp.async.cg.shared.global [%0], [%1], 16;" :: "r"(dst), "l"(src)); \
    } \
} while (0)
#define CP_COMMIT() asm volatile("cp.async.commit_group;" ::: "memory")
#define CP_WAIT2()  asm volatile("cp.async.wait_group 2;" ::: "memory")

__global__ __launch_bounds__(256, 2) void gemm_tokens_mma(const float* __restrict__ bias) {
    extern __shared__ char smc[];
    __half* sm = (__half*)smc;
    const int tid  = threadIdx.x;
    const int lane = tid & 31, wid = tid >> 5;
    const int wm = wid & 3, wn = wid >> 2;
    const int seg = lane >> 3;
    const int n0 = blockIdx.x * 128;
    const int m0 = blockIdx.y * 128;

    float c[2][8][4] = {};

    GEMM_ISSUE(0); CP_COMMIT();
    GEMM_ISSUE(1); CP_COMMIT();
    GEMM_ISSUE(2); CP_COMMIT();

    for (int kt = 0; kt < 12; kt++) {
        CP_WAIT2();
        __syncthreads();
        __half* st = sm + (kt % 3) * GST;
#pragma unroll
        for (int ks = 0; ks < 4; ks++) {
            const int k0 = ks * 16;
            uint32_t a[2][4];
#pragma unroll
            for (int mf = 0; mf < 2; mf++) {
                int r = wm * 32 + mf * 16 + (lane & 15);
                int ko = k0 + (lane >> 4) * 8;
                LDSM4(a[mf], smem_u32(&st[r * KS + ko]));
            }
#pragma unroll
            for (int nf2 = 0; nf2 < 4; nf2++) {
                int r = wn * 64 + nf2 * 16 + (seg >> 1) * 8 + (lane & 7);
                int ko = k0 + (seg & 1) * 8;
                uint32_t bfr[4];
                LDSM4(bfr, smem_u32(&st[128 * KS + r * KS + ko]));
#pragma unroll
                for (int mf = 0; mf < 2; mf++) {
                    mma_f16(c[mf][nf2 * 2 + 0], a[mf], bfr + 0);
                    mma_f16(c[mf][nf2 * 2 + 1], a[mf], bfr + 2);
                }
            }
        }
        __syncthreads();
        if (kt + 3 < 12) GEMM_ISSUE(kt + 3);
        CP_COMMIT();
    }

#pragma unroll
    for (int mf = 0; mf < 2; mf++) {
#pragma unroll
        for (int half = 0; half < 2; half++) {
            int mg = m0 + wm * 32 + mf * 16 + (lane >> 2) + half * 8;
            int b = mg / NPAT, p = mg % NPAT;
            float* orow = g_tokens + ((size_t)b * SEQL + p + 1) * HD;
            const float* prow = g_pos + (size_t)(p + 1) * HD;
#pragma unroll
            for (int nf = 0; nf < 8; nf++) {
                int col = n0 + wn * 64 + nf * 8 + (lane & 3) * 2;
                float2 o;
                o.x = c[mf][nf][half * 2 + 0] + bias[col] + prow[col];
                o.y = c[mf][nf][half * 2 + 1] + bias[col + 1] + prow[col + 1];
                *(float2*)(orow + col) = o;
            }
        }
    }
}

// ---------------- per-sample LN stats ----------------
__global__ __launch_bounds__(1024) void stats_kernel() {
    int b = blockIdx.x;
    const float4* base = (const float4*)(g_tokens + (size_t)b * SEQL * HD);
    const int n4 = SEQL * HD / 4;
    float s = 0.f, sq = 0.f;
    for (int i = threadIdx.x; i < n4; i += 1024) {
        float4 v = base[i];
        s  += v.x + v.y + v.z + v.w;
        sq += v.x * v.x + v.y * v.y + v.z * v.z + v.w * v.w;
    }
    __shared__ float sh[64];
#pragma unroll
    for (int o = 16; o; o >>= 1) {
        s  += __shfl_xor_sync(0xffffffffu, s, o);
        sq += __shfl_xor_sync(0xffffffffu, sq, o);
    }
    int w = threadIdx.x >> 5, l = threadIdx.x & 31;
    if (!l) { sh[w] = s; sh[32 + w] = sq; }
    __syncthreads();
    if (threadIdx.x == 0) {
        float S = 0.f, Q = 0.f;
        for (int i = 0; i < 32; i++) { S += sh[i]; Q += sh[32 + i]; }
        const float n = (float)(SEQL * HD);
        float mean = S / n;
        float var  = Q / n - mean * mean;
        g_mean[b] = mean;
        g_rstd[b] = rsqrtf(var + LN_EPS);
    }
}

// ---------------- fused QKV + attention: 416 threads = 13 warps ----------------
// Warp w: phase1 computes q/k/v for m-tile w (3 tasks); phase2 attention tile w.
#define NTH  416
#define SEQP 208
#define QKS  72
#define VTS  216
#define FX  0
#define FW  (SEQP * QKS)
#define FK  (SEQP * QKS + 192 * QKS)
#define FQ  (FK + SEQP * QKS)
#define FVT (FQ + SEQP * QKS)
#define FUSED_SMEM ((FVT + 64 * VTS) * 2)

__global__ void __launch_bounds__(NTH, 1) qkv_attn_fused(
    const float* __restrict__ lnw, const float* __restrict__ lnb,
    const float* __restrict__ Wq, const float* __restrict__ bq,
    const float* __restrict__ Wk, const float* __restrict__ bk,
    const float* __restrict__ Wv, const float* __restrict__ bv,
    float* __restrict__ out) {
    extern __shared__ __half fsm[];
    const int tid = threadIdx.x, lane = tid & 31, w = tid >> 5;
    const int seg = lane >> 3;
    const int bh = blockIdx.x, b = bh / NH, h = bh % NH;
    const float mean = g_mean[b], rstd = g_rstd[b];
    const float* tb = g_tokens + (size_t)b * SEQL * HD + h * DH;

    // ---- phase 0: stage X normalized (fp16) and W (fp16) ----
    for (int idx = tid; idx < SEQP * 16; idx += NTH) {
        int s = idx >> 4, d4 = (idx & 15) * 4;
        float4 x = {0.f, 0.f, 0.f, 0.f};
        if (s < SEQL) {
            float4 tv = *(const float4*)(tb + (size_t)s * HD + d4);
            float4 wv = *(const float4*)(lnw + (size_t)s * HD + h * DH + d4);
            float4 bb = *(const float4*)(lnb + (size_t)s * HD + h * DH + d4);
            x.x = (tv.x - mean) * rstd * wv.x + bb.x;
            x.y = (tv.y - mean) * rstd * wv.y + bb.y;
            x.z = (tv.z - mean) * rstd * wv.z + bb.z;
            x.w = (tv.w - mean) * rstd * wv.w + bb.w;
        }
        *(uint2*)&fsm[FX + s * QKS + d4] = cvt_f4(x);
    }
    for (int idx = tid; idx < 3 * 64 * 16; idx += NTH) {
        int m = idx >> 10, rem = idx & 1023;
        int e = rem >> 4, d4 = (rem & 15) * 4;
        const float* Wsrc = (m == 0 ? Wq : (m == 1 ? Wk : Wv)) + (size_t)h * DH * DH;
        float4 v = *(const float4*)(Wsrc + e * DH + d4);
        *(uint2*)&fsm[FW + (m * 64 + e) * QKS + d4] = cvt_f4(v);
    }
    __syncthreads();

    // ---- phase 1: warp w does q/k/v for tile w ----
    {
        const int mt = w;
#pragma unroll
        for (int m = 0; m < 3; m++) {
            float c[8][4] = {};
#pragma unroll
            for (int ks = 0; ks < 4; ks++) {
                const int k0 = ks * 16;
                uint32_t a[4];
                {
                    int r = mt * 16 + (lane & 15);
                    int ko = k0 + (lane >> 4) * 8;
                    LDSM4(a, smem_u32(&fsm[FX + r * QKS + ko]));
                }
#pragma unroll
                for (int nf2 = 0; nf2 < 4; nf2++) {
                    int r = m * 64 + nf2 * 16 + (seg >> 1) * 8 + (lane & 7);
                    int ko = k0 + (seg & 1) * 8;
                    uint32_t bfr[4];
                    LDSM4(bfr, smem_u32(&fsm[FW + r * QKS + ko]));
                    mma_f16(c[nf2 * 2 + 0], a, bfr + 0);
                    mma_f16(c[nf2 * 2 + 1], a, bfr + 2);
                }
            }
            const float* bias = (m == 0 ? bq : (m == 1 ? bk : bv)) + h * DH;
            int r0 = mt * 16 + (lane >> 2);
#pragma unroll
            for (int half = 0; half < 2; half++) {
                int r = r0 + half * 8;   // < 208; padded rows hold bias (inert)
#pragma unroll
                for (int nf = 0; nf < 8; nf++) {
                    int e = nf * 8 + (lane & 3) * 2;
                    float v0 = c[nf][half * 2 + 0] + bias[e];
                    float v1 = c[nf][half * 2 + 1] + bias[e + 1];
                    if (m == 0) {
                        *(uint32_t*)&fsm[FQ + r * QKS + e] = pack_h_f(v0 * 0.125f, v1 * 0.125f);
                    } else if (m == 1) {
                        *(uint32_t*)&fsm[FK + r * QKS + e] = pack_h_f(v0, v1);
                    } else {
                        fsm[FVT + e * VTS + r] = __float2half_rn(v0);
                        fsm[FVT + (e + 1) * VTS + r] = __float2half_rn(v1);
                    }
                }
            }
        }
    }
    __syncthreads();

    // ---- phase 2: attention, one m-tile per warp ----
    {
        const int mt = w;
        float c[26][4];
#pragma unroll
        for (int nf = 0; nf < 26; nf++)
            c[nf][0] = c[nf][1] = c[nf][2] = c[nf][3] = 0.f;

        // S = Qs * K^T
#pragma unroll
        for (int ksx = 0; ksx < 4; ksx++) {
            uint32_t a[4];
            {
                int r = mt * 16 + (lane & 15);
                int co = ksx * 16 + (lane >> 4) * 8;
                LDSM4(a, smem_u32(&fsm[FQ + r * QKS + co]));
            }
#pragma unroll
            for (int nf2 = 0; nf2 < 13; nf2++) {
                int r = nf2 * 16 + (seg >> 1) * 8 + (lane & 7);
                int co = ksx * 16 + (seg & 1) * 8;
                uint32_t t4[4];
                LDSM4(t4, smem_u32(&fsm[FK + r * QKS + co]));
                mma_f16(c[2 * nf2 + 0], a, t4 + 0);
                mma_f16(c[2 * nf2 + 1], a, t4 + 2);
            }
        }

        // mask padded columns (cols >= 197)
        {
            int cb = (lane & 3) * 2;
            if (192 + cb >= SEQL) { c[24][0] = -1e30f; c[24][2] = -1e30f; }
            if (193 + cb >= SEQL) { c[24][1] = -1e30f; c[24][3] = -1e30f; }
            c[25][0] = c[25][1] = c[25][2] = c[25][3] = -1e30f;
        }

        // softmax in registers
        float mx0 = -1e30f, mx1 = -1e30f;
#pragma unroll
        for (int nf = 0; nf < 26; nf++) {
            mx0 = fmaxf(mx0, fmaxf(c[nf][0], c[nf][1]));
            mx1 = fmaxf(mx1, fmaxf(c[nf][2], c[nf][3]));
        }
        mx0 = fmaxf(mx0, __shfl_xor_sync(0xffffffffu, mx0, 1));
        mx0 = fmaxf(mx0, __shfl_xor_sync(0xffffffffu, mx0, 2));
        mx1 = fmaxf(mx1, __shfl_xor_sync(0xffffffffu, mx1, 1));
        mx1 = fmaxf(mx1, __shfl_xor_sync(0xffffffffu, mx1, 2));
        float s0 = 0.f, s1 = 0.f;
#pragma unroll
        for (int nf = 0; nf < 26; nf++) {
            c[nf][0] = __expf(c[nf][0] - mx0); s0 += c[nf][0];
            c[nf][1] = __expf(c[nf][1] - mx0); s0 += c[nf][1];
            c[nf][2] = __expf(c[nf][2] - mx1); s1 += c[nf][2];
            c[nf][3] = __expf(c[nf][3] - mx1); s1 += c[nf][3];
        }
        s0 += __shfl_xor_sync(0xffffffffu, s0, 1);
        s0 += __shfl_xor_sync(0xffffffffu, s0, 2);
        s1 += __shfl_xor_sync(0xffffffffu, s1, 1);
        s1 += __shfl_xor_sync(0xffffffffu, s1, 2);
        float inv0 = 1.0f / s0, inv1 = 1.0f / s1;

        // O = P * V^T
        float o[8][4];
#pragma unroll
        for (int ne = 0; ne < 8; ne++)
            o[ne][0] = o[ne][1] = o[ne][2] = o[ne][3] = 0.f;

#pragma unroll
        for (int kt = 0; kt < 13; kt++) {
            uint32_t pa[4];
            pa[0] = pack_h_f(c[2 * kt][0] * inv0, c[2 * kt][1] * inv0);
            pa[1] = pack_h_f(c[2 * kt][2] * inv1, c[2 * kt][3] * inv1);
            pa[2] = pack_h_f(c[2 * kt + 1][0] * inv0, c[2 * kt + 1][1] * inv0);
            pa[3] = pack_h_f(c[2 * kt + 1][2] * inv1, c[2 * kt + 1][3] * inv1);
#pragma unroll
            for (int ne2 = 0; ne2 < 4; ne2++) {
                int r = ne2 * 16 + (seg >> 1) * 8 + (lane & 7);
                int co = kt * 16 + (seg & 1) * 8;
                uint32_t t4[4];
                LDSM4(t4, smem_u32(&fsm[FVT + r * VTS + co]));
                mma_f16(o[2 * ne2 + 0], pa, t4 + 0);
                mma_f16(o[2 * ne2 + 1], pa, t4 + 2);
            }
        }

        // epilogue: residual add, guarded stores
        int r0 = mt * 16 + (lane >> 2);
        int cb = (lane & 3) * 2;
        if (r0 < SEQL) {
            size_t base = ((size_t)b * SEQL + r0) * HD + h * DH;
#pragma unroll
            for (int ne = 0; ne < 8; ne++) {
                int n = ne * 8 + cb;
                float2 t = *(const float2*)(g_tokens + base + n);
                float2 ov = {t.x + o[ne][0], t.y + o[ne][1]};
                *(float2*)(out + base + n) = ov;
            }
        }
        if (r0 + 8 < SEQL) {
            size_t base = ((size_t)b * SEQL + r0 + 8) * HD + h * DH;
#pragma unroll
            for (int ne = 0; ne < 8; ne++) {
                int n = ne * 8 + cb;
                float2 t = *(const float2*)(g_tokens + base + n);
                float2 ov = {t.x + o[ne][2], t.y + o[ne][3]};
                *(float2*)(out + base + n) = ov;
            }
        }
    }
}

// ---------------- launcher ----------------
extern "C" void kernel_launch(void* const* d_in, const int* in_sizes, int n_in,
                              void* d_out, int out_size) {
    const float* images = (const float*)d_in[0];
    const float* W_map  = (const float*)d_in[1];
    const float* b_map  = (const float*)d_in[2];
    const float* cls    = (const float*)d_in[3];
    const float* ln_w   = (const float*)d_in[4];
    const float* ln_b   = (const float*)d_in[5];
    const float* Wq     = (const float*)d_in[6];
    const float* bq     = (const float*)d_in[7];
    const float* Wk     = (const float*)d_in[8];
    const float* bk     = (const float*)d_in[9];
    const float* Wv     = (const float*)d_in[10];
    const float* bv     = (const float*)d_in[11];
    float* out = (float*)d_out;

    cudaFuncSetAttribute(gemm_tokens_mma, cudaFuncAttributeMaxDynamicSharedMemorySize, G_SMEM);
    cudaFuncSetAttribute(qkv_attn_fused, cudaFuncAttributeMaxDynamicSharedMemorySize, FUSED_SMEM);

    pos_kernel<<<(SEQL * HD + 255) / 256, 256>>>();
    cls_kernel<<<NB, 256>>>(cls);
    cvt_kernel<<<4736, 256>>>(images, W_map);
    gemm_tokens_mma<<<dim3(HD / 128, (NB * NPAT) / 128), 256, G_SMEM>>>(b_map);
    stats_kernel<<<NB, 1024>>>();
    qkv_attn_fused<<<NB * NH, NTH, FUSED_SMEM>>>(ln_w, ln_b, Wq, bq, Wk, bk, Wv, bv, out);
}

// round 13
// speedup vs baseline: 6.6290x; 1.0637x over previous
#include <cuda_runtime.h>
#include <cuda_fp16.h>
#include <math.h>
#include <stdint.h>

#define NB   128
#define SEQL 197
#define NPAT 196
#define HD   768
#define NH   12
#define DH   64
#define LN_EPS 1e-5f
#define NA   (NB * NPAT * HD)   // 19267584 image elems
#define NW   (HD * HD)

// ---------------- scratch (static device globals; no allocs) ----------------
static __device__ float g_tokens[NB * SEQL * HD];          // 77.4 MB
static __device__ float g_pos[SEQL * HD];
static __device__ float g_mean[NB];
static __device__ float g_rstd[NB];
static __device__ __half g_Ah[NA];                          // fp16 images
static __device__ __half g_Wh[NW];                          // fp16 W_map

// ================= helpers =================
__device__ __forceinline__ uint32_t smem_u32(const void* p) {
    uint32_t a;
    asm("{ .reg .u64 t; cvta.to.shared.u64 t, %1; cvt.u32.u64 %0, t; }" : "=r"(a) : "l"(p));
    return a;
}
#define LDSM4(r, addr) \
    asm volatile("ldmatrix.sync.aligned.m8n8.x4.shared.b16 {%0,%1,%2,%3}, [%4];" \
        : "=r"((r)[0]), "=r"((r)[1]), "=r"((r)[2]), "=r"((r)[3]) : "r"(addr))

__device__ __forceinline__ void mma_f16(float* c, const uint32_t* a, const uint32_t* b) {
    asm volatile("mma.sync.aligned.m16n8k16.row.col.f32.f16.f16.f32 "
        "{%0,%1,%2,%3}, {%4,%5,%6,%7}, {%8,%9}, {%0,%1,%2,%3};"
        : "+f"(c[0]), "+f"(c[1]), "+f"(c[2]), "+f"(c[3])
        : "r"(a[0]), "r"(a[1]), "r"(a[2]), "r"(a[3]), "r"(b[0]), "r"(b[1]));
}

__device__ __forceinline__ uint32_t pack_h_f(float x, float y) {
    __half2 t = __floats2half2_rn(x, y);
    return *(uint32_t*)&t;
}
__device__ __forceinline__ uint2 cvt_f4(float4 v) {
    uint2 r;
    r.x = pack_h_f(v.x, v.y);
    r.y = pack_h_f(v.z, v.w);
    return r;
}
__device__ __forceinline__ uint32_t ex2_h2(uint32_t y) {
    uint32_t r;
    asm("ex2.approx.f16x2 %0, %1;" : "=r"(r) : "r"(y));
    return r;
}
__device__ __forceinline__ uint32_t hmul2_u(uint32_t a, uint32_t b) {
    __half2 t = __hmul2(*(__half2*)&a, *(__half2*)&b);
    return *(uint32_t*)&t;
}

// ---------------- positional embeddings ----------------
__global__ void pos_kernel() {
    int idx = blockIdx.x * blockDim.x + threadIdx.x;
    if (idx >= SEQL * HD) return;
    int i = idx / HD, j = idx % HD;
    float jf = (float)(j & ~1);
    float denom = powf(10000.0f, jf / (float)HD);
    float arg = (float)i / denom;
    g_pos[idx] = (j & 1) ? cosf(arg) : sinf(arg);
}

// ---------------- class token row ----------------
__global__ void cls_kernel(const float* __restrict__ cls) {
    int b = blockIdx.x;
    for (int j = threadIdx.x; j < HD; j += blockDim.x)
        g_tokens[(size_t)b * SEQL * HD + j] = cls[j] + g_pos[j];
}

// ---------------- fp32 -> fp16 pre-convert (images + W_map) ----------------
__global__ __launch_bounds__(256) void cvt_kernel(const float* __restrict__ A,
                                                  const float* __restrict__ Wm) {
    const int stride = gridDim.x * blockDim.x;
    const int tot4 = (NA + NW) / 4;
    for (int i = blockIdx.x * blockDim.x + threadIdx.x; i < tot4; i += stride) {
        if (i < NA / 4) {
            float4 v = ((const float4*)A)[i];
            *(uint2*)&g_Ah[(size_t)i * 4] = cvt_f4(v);
        } else {
            int j = i - NA / 4;
            float4 v = ((const float4*)Wm)[j];
            *(uint2*)&g_Wh[(size_t)j * 4] = cvt_f4(v);
        }
    }
}

// ---------------- token projection GEMM: fp16 mma + cp.async, 1 sync/iter -----
// C[m,n] = sum_k A[m,k]*W[n,k]; M=25088, N=768, K=768.
// CTA tile 128x128, BK=64, 8 warps (4m x 2n), warp tile 32x64. 2 CTA/SM.
// Depth-2 pipeline over 3 stages: wait 1 -> sync -> issue kt+2 -> compute kt.
#define KS 72
#define GST (256 * KS)            // halves per stage: A[128][72] + W[128][72]
#define G_SMEM (3 * GST * 2)      // 110592 bytes

#define GEMM_ISSUE(ktile) do { \
    __half* st_ = sm + ((ktile) % 3) * GST; \
    const int kb_ = (ktile) * 64; \
    _Pragma("unroll") \
    for (int it = 0; it < 8; it++) { \
        int ch = it * 256 + tid; \
        int row = ch >> 3, c8 = ch & 7; \
        const __half* src = (row < 128) \
            ? (g_Ah + (size_t)(m0 + row) * HD + kb_ + c8 * 8) \
            : (g_Wh + (size_t)(n0 + row - 128) * HD + kb_ + c8 * 8); \
        uint32_t dst = smem_u32(&st_[row * KS + c8 * 8]); \
        asm volatile("cp.async.cg.shared.global [%0], [%1], 16;" :: "r"(dst), "l"(src)); \
    } \
} while (0)
#define CP_COMMIT() asm volatile("cp.async.commit_group;" ::: "memory")
#define CP_WAIT1()  asm volatile("cp.async.wait_group 1;" ::: "memory")

__global__ __launch_bounds__(256, 2) void gemm_tokens_mma(const float* __restrict__ bias) {
    extern __shared__ char smc[];
    __half* sm = (__half*)smc;
    const int tid  = threadIdx.x;
    const int lane = tid & 31, wid = tid >> 5;
    const int wm = wid & 3, wn = wid >> 2;
    const int seg = lane >> 3;
    const int n0 = blockIdx.x * 128;
    const int m0 = blockIdx.y * 128;

    float c[2][8][4] = {};

    GEMM_ISSUE(0); CP_COMMIT();
    GEMM_ISSUE(1); CP_COMMIT();

    for (int kt = 0; kt < 12; kt++) {
        CP_WAIT1();              // tile kt complete (only kt+1 may remain in flight)
        __syncthreads();         // all warps past compute of kt-1 -> slot (kt+2)%3 free
        if (kt + 2 < 12) GEMM_ISSUE(kt + 2);
        CP_COMMIT();
        __half* st = sm + (kt % 3) * GST;
#pragma unroll
        for (int ks = 0; ks < 4; ks++) {
            const int k0 = ks * 16;
            uint32_t a[2][4];
#pragma unroll
            for (int mf = 0; mf < 2; mf++) {
                int r = wm * 32 + mf * 16 + (lane & 15);
                int ko = k0 + (lane >> 4) * 8;
                LDSM4(a[mf], smem_u32(&st[r * KS + ko]));
            }
#pragma unroll
            for (int nf2 = 0; nf2 < 4; nf2++) {
                int r = wn * 64 + nf2 * 16 + (seg >> 1) * 8 + (lane & 7);
                int ko = k0 + (seg & 1) * 8;
                uint32_t bfr[4];
                LDSM4(bfr, smem_u32(&st[128 * KS + r * KS + ko]));
#pragma unroll
                for (int mf = 0; mf < 2; mf++) {
                    mma_f16(c[mf][nf2 * 2 + 0], a[mf], bfr + 0);
                    mma_f16(c[mf][nf2 * 2 + 1], a[mf], bfr + 2);
                }
            }
        }
    }

#pragma unroll
    for (int mf = 0; mf < 2; mf++) {
#pragma unroll
        for (int half = 0; half < 2; half++) {
            int mg = m0 + wm * 32 + mf * 16 + (lane >> 2) + half * 8;
            int b = mg / NPAT, p = mg % NPAT;
            float* orow = g_tokens + ((size_t)b * SEQL + p + 1) * HD;
            const float* prow = g_pos + (size_t)(p + 1) * HD;
#pragma unroll
            for (int nf = 0; nf < 8; nf++) {
                int col = n0 + wn * 64 + nf * 8 + (lane & 3) * 2;
                float2 o;
                o.x = c[mf][nf][half * 2 + 0] + bias[col] + prow[col];
                o.y = c[mf][nf][half * 2 + 1] + bias[col + 1] + prow[col + 1];
                *(float2*)(orow + col) = o;
            }
        }
    }
}

// ---------------- per-sample LN stats ----------------
__global__ __launch_bounds__(1024) void stats_kernel() {
    int b = blockIdx.x;
    const float4* base = (const float4*)(g_tokens + (size_t)b * SEQL * HD);
    const int n4 = SEQL * HD / 4;
    float s = 0.f, sq = 0.f;
    for (int i = threadIdx.x; i < n4; i += 1024) {
        float4 v = base[i];
        s  += v.x + v.y + v.z + v.w;
        sq += v.x * v.x + v.y * v.y + v.z * v.z + v.w * v.w;
    }
    __shared__ float sh[64];
#pragma unroll
    for (int o = 16; o; o >>= 1) {
        s  += __shfl_xor_sync(0xffffffffu, s, o);
        sq += __shfl_xor_sync(0xffffffffu, sq, o);
    }
    int w = threadIdx.x >> 5, l = threadIdx.x & 31;
    if (!l) { sh[w] = s; sh[32 + w] = sq; }
    __syncthreads();
    if (threadIdx.x == 0) {
        float S = 0.f, Q = 0.f;
        for (int i = 0; i < 32; i++) { S += sh[i]; Q += sh[32 + i]; }
        const float n = (float)(SEQL * HD);
        float mean = S / n;
        float var  = Q / n - mean * mean;
        g_mean[b] = mean;
        g_rstd[b] = rsqrtf(var + LN_EPS);
    }
}

// ---------------- fused QKV + attention: 416 threads = 13 warps ----------------
#define NTH  416
#define SEQP 208
#define QKS  72
#define VTS  216
#define FX  0
#define FW  (SEQP * QKS)
#define FK  (SEQP * QKS + 192 * QKS)
#define FQ  (FK + SEQP * QKS)
#define FVT (FQ + SEQP * QKS)
#define FUSED_SMEM ((FVT + 64 * VTS) * 2)

__global__ void __launch_bounds__(NTH, 1) qkv_attn_fused(
    const float* __restrict__ lnw, const float* __restrict__ lnb,
    const float* __restrict__ Wq, const float* __restrict__ bq,
    const float* __restrict__ Wk, const float* __restrict__ bk,
    const float* __restrict__ Wv, const float* __restrict__ bv,
    float* __restrict__ out) {
    extern __shared__ __half fsm[];
    const int tid = threadIdx.x, lane = tid & 31, w = tid >> 5;
    const int seg = lane >> 3;
    const int bh = blockIdx.x, b = bh / NH, h = bh % NH;
    const float mean = g_mean[b], rstd = g_rstd[b];
    const float* tb = g_tokens + (size_t)b * SEQL * HD + h * DH;

    // ---- phase 0: stage X normalized (fp16) and W (fp16) ----
    for (int idx = tid; idx < SEQP * 16; idx += NTH) {
        int s = idx >> 4, d4 = (idx & 15) * 4;
        float4 x = {0.f, 0.f, 0.f, 0.f};
        if (s < SEQL) {
            float4 tv = *(const float4*)(tb + (size_t)s * HD + d4);
            float4 wv = *(const float4*)(lnw + (size_t)s * HD + h * DH + d4);
            float4 bb = *(const float4*)(lnb + (size_t)s * HD + h * DH + d4);
            x.x = (tv.x - mean) * rstd * wv.x + bb.x;
            x.y = (tv.y - mean) * rstd * wv.y + bb.y;
            x.z = (tv.z - mean) * rstd * wv.z + bb.z;
            x.w = (tv.w - mean) * rstd * wv.w + bb.w;
        }
        *(uint2*)&fsm[FX + s * QKS + d4] = cvt_f4(x);
    }
    for (int idx = tid; idx < 3 * 64 * 16; idx += NTH) {
        int m = idx >> 10, rem = idx & 1023;
        int e = rem >> 4, d4 = (rem & 15) * 4;
        const float* Wsrc = (m == 0 ? Wq : (m == 1 ? Wk : Wv)) + (size_t)h * DH * DH;
        float4 v = *(const float4*)(Wsrc + e * DH + d4);
        *(uint2*)&fsm[FW + (m * 64 + e) * QKS + d4] = cvt_f4(v);
    }
    __syncthreads();

    // ---- phase 1: warp w does q/k/v for tile w (A-frags hoisted) ----
    {
        const int mt = w;
        uint32_t af[4][4];
#pragma unroll
        for (int ks = 0; ks < 4; ks++) {
            int r = mt * 16 + (lane & 15);
            int ko = ks * 16 + (lane >> 4) * 8;
            LDSM4(af[ks], smem_u32(&fsm[FX + r * QKS + ko]));
        }
#pragma unroll
        for (int m = 0; m < 3; m++) {
            float c[8][4] = {};
#pragma unroll
            for (int ks = 0; ks < 4; ks++) {
                const int k0 = ks * 16;
#pragma unroll
                for (int nf2 = 0; nf2 < 4; nf2++) {
                    int r = m * 64 + nf2 * 16 + (seg >> 1) * 8 + (lane & 7);
                    int ko = k0 + (seg & 1) * 8;
                    uint32_t bfr[4];
                    LDSM4(bfr, smem_u32(&fsm[FW + r * QKS + ko]));
                    mma_f16(c[nf2 * 2 + 0], af[ks], bfr + 0);
                    mma_f16(c[nf2 * 2 + 1], af[ks], bfr + 2);
                }
            }
            const float* bias = (m == 0 ? bq : (m == 1 ? bk : bv)) + h * DH;
            int r0 = mt * 16 + (lane >> 2);
#pragma unroll
            for (int half = 0; half < 2; half++) {
                int r = r0 + half * 8;   // < 208; padded rows hold bias (inert)
#pragma unroll
                for (int nf = 0; nf < 8; nf++) {
                    int e = nf * 8 + (lane & 3) * 2;
                    float v0 = c[nf][half * 2 + 0] + bias[e];
                    float v1 = c[nf][half * 2 + 1] + bias[e + 1];
                    if (m == 0) {
                        *(uint32_t*)&fsm[FQ + r * QKS + e] = pack_h_f(v0 * 0.125f, v1 * 0.125f);
                    } else if (m == 1) {
                        *(uint32_t*)&fsm[FK + r * QKS + e] = pack_h_f(v0, v1);
                    } else {
                        fsm[FVT + e * VTS + r] = __float2half_rn(v0);
                        fsm[FVT + (e + 1) * VTS + r] = __float2half_rn(v1);
                    }
                }
            }
        }
    }
    __syncthreads();

    // ---- phase 2: attention, one m-tile per warp ----
    {
        const int mt = w;
        float c[26][4];
#pragma unroll
        for (int nf = 0; nf < 26; nf++)
            c[nf][0] = c[nf][1] = c[nf][2] = c[nf][3] = 0.f;

        // S = Qs * K^T
#pragma unroll
        for (int ksx = 0; ksx < 4; ksx++) {
            uint32_t a[4];
            {
                int r = mt * 16 + (lane & 15);
                int co = ksx * 16 + (lane >> 4) * 8;
                LDSM4(a, smem_u32(&fsm[FQ + r * QKS + co]));
            }
#pragma unroll
            for (int nf2 = 0; nf2 < 13; nf2++) {
                int r = nf2 * 16 + (seg >> 1) * 8 + (lane & 7);
                int co = ksx * 16 + (seg & 1) * 8;
                uint32_t t4[4];
                LDSM4(t4, smem_u32(&fsm[FK + r * QKS + co]));
                mma_f16(c[2 * nf2 + 0], a, t4 + 0);
                mma_f16(c[2 * nf2 + 1], a, t4 + 2);
            }
        }

        // mask padded columns (cols >= 197)
        {
            int cb = (lane & 3) * 2;
            if (192 + cb >= SEQL) { c[24][0] = -1e30f; c[24][2] = -1e30f; }
            if (193 + cb >= SEQL) { c[24][1] = -1e30f; c[24][3] = -1e30f; }
            c[25][0] = c[25][1] = c[25][2] = c[25][3] = -1e30f;
        }

        // softmax: row max, then P = 2^(L2E*(s - mx)) via ex2.approx.f16x2
        float mx0 = -1e30f, mx1 = -1e30f;
#pragma unroll
        for (int nf = 0; nf < 26; nf++) {
            mx0 = fmaxf(mx0, fmaxf(c[nf][0], c[nf][1]));
            mx1 = fmaxf(mx1, fmaxf(c[nf][2], c[nf][3]));
        }
        mx0 = fmaxf(mx0, __shfl_xor_sync(0xffffffffu, mx0, 1));
        mx0 = fmaxf(mx0, __shfl_xor_sync(0xffffffffu, mx0, 2));
        mx1 = fmaxf(mx1, __shfl_xor_sync(0xffffffffu, mx1, 1));
        mx1 = fmaxf(mx1, __shfl_xor_sync(0xffffffffu, mx1, 2));

        const float L2E = 1.4426950408889634f;
        const float b0 = mx0 * L2E, b1 = mx1 * L2E;
        uint32_t ph[26][2];
        float s0 = 0.f, s1 = 0.f;
#pragma unroll
        for (int nf = 0; nf < 26; nf++) {
            uint32_t y0 = pack_h_f(fmaf(c[nf][0], L2E, -b0), fmaf(c[nf][1], L2E, -b0));
            uint32_t y1 = pack_h_f(fmaf(c[nf][2], L2E, -b1), fmaf(c[nf][3], L2E, -b1));
            ph[nf][0] = ex2_h2(y0);
            ph[nf][1] = ex2_h2(y1);
            float2 f0 = __half22float2(*(__half2*)&ph[nf][0]);
            float2 f1 = __half22float2(*(__half2*)&ph[nf][1]);
            s0 += f0.x + f0.y;
            s1 += f1.x + f1.y;
        }
        s0 += __shfl_xor_sync(0xffffffffu, s0, 1);
        s0 += __shfl_xor_sync(0xffffffffu, s0, 2);
        s1 += __shfl_xor_sync(0xffffffffu, s1, 1);
        s1 += __shfl_xor_sync(0xffffffffu, s1, 2);
        float inv0 = 1.0f / s0, inv1 = 1.0f / s1;
        uint32_t ih0 = pack_h_f(inv0, inv0);
        uint32_t ih1 = pack_h_f(inv1, inv1);

        // O = P * V^T
        float o[8][4];
#pragma unroll
        for (int ne = 0; ne < 8; ne++)
            o[ne][0] = o[ne][1] = o[ne][2] = o[ne][3] = 0.f;

#pragma unroll
        for (int kt = 0; kt < 13; kt++) {
            uint32_t pa[4];
            pa[0] = hmul2_u(ph[2 * kt][0], ih0);
            pa[1] = hmul2_u(ph[2 * kt][1], ih1);
            pa[2] = hmul2_u(ph[2 * kt + 1][0], ih0);
            pa[3] = hmul2_u(ph[2 * kt + 1][1], ih1);
#pragma unroll
            for (int ne2 = 0; ne2 < 4; ne2++) {
                int r = ne2 * 16 + (seg >> 1) * 8 + (lane & 7);
                int co = kt * 16 + (seg & 1) * 8;
                uint32_t t4[4];
                LDSM4(t4, smem_u32(&fsm[FVT + r * VTS + co]));
                mma_f16(o[2 * ne2 + 0], pa, t4 + 0);
                mma_f16(o[2 * ne2 + 1], pa, t4 + 2);
            }
        }

        // epilogue: residual add, guarded stores
        int r0 = mt * 16 + (lane >> 2);
        int cb = (lane & 3) * 2;
        if (r0 < SEQL) {
            size_t base = ((size_t)b * SEQL + r0) * HD + h * DH;
#pragma unroll
            for (int ne = 0; ne < 8; ne++) {
                int n = ne * 8 + cb;
                float2 t = *(const float2*)(g_tokens + base + n);
                float2 ov = {t.x + o[ne][0], t.y + o[ne][1]};
                *(float2*)(out + base + n) = ov;
            }
        }
        if (r0 + 8 < SEQL) {
            size_t base = ((size_t)b * SEQL + r0 + 8) * HD + h * DH;
#pragma unroll
            for (int ne = 0; ne < 8; ne++) {
                int n = ne * 8 + cb;
                float2 t = *(const float2*)(g_tokens + base + n);
                float2 ov = {t.x + o[ne][2], t.y + o[ne][3]};
                *(float2*)(out + base + n) = ov;
            }
        }
    }
}

// ---------------- launcher ----------------
extern "C" void kernel_launch(void* const* d_in, const int* in_sizes, int n_in,
                              void* d_out, int out_size) {
    const float* images = (const float*)d_in[0];
    const float* W_map  = (const float*)d_in[1];
    const float* b_map  = (const float*)d_in[2];
    const float* cls    = (const float*)d_in[3];
    const float* ln_w   = (const float*)d_in[4];
    const float* ln_b   = (const float*)d_in[5];
    const float* Wq     = (const float*)d_in[6];
    const float* bq     = (const float*)d_in[7];
    const float* Wk     = (const float*)d_in[8];
    const float* bk     = (const float*)d_in[9];
    const float* Wv     = (const float*)d_in[10];
    const float* bv     = (const float*)d_in[11];
    float* out = (float*)d_out;

    cudaFuncSetAttribute(gemm_tokens_mma, cudaFuncAttributeMaxDynamicSharedMemorySize, G_SMEM);
    cudaFuncSetAttribute(qkv_attn_fused, cudaFuncAttributeMaxDynamicSharedMemorySize, FUSED_SMEM);

    pos_kernel<<<(SEQL * HD + 255) / 256, 256>>>();
    cls_kernel<<<NB, 256>>>(cls);
    cvt_kernel<<<4736, 256>>>(images, W_map);
    gemm_tokens_mma<<<dim3(HD / 128, (NB * NPAT) / 128), 256, G_SMEM>>>(b_map);
    stats_kernel<<<NB, 1024>>>();
    qkv_attn_fused<<<NB * NH, NTH, FUSED_SMEM>>>(ln_w, ln_b, Wq, bq, Wk, bk, Wv, bv, out);
}